// round 1
// baseline (speedup 1.0000x reference)
#include <cuda_runtime.h>
#include <math.h>

#define BATCH 32768
#define D_IN  1024
#define D_H   1024
#define D_L   128

// Scratch (alloc-free rule: __device__ globals)
__device__ __align__(16) float g_h [BATCH * D_H];
__device__ __align__(16) float g_mu[BATCH * D_L];
__device__ __align__(16) float g_ls[BATCH * D_L];
__device__ __align__(16) float g_z [BATCH * D_L];
__device__ __align__(16) float g_hd[BATCH * D_H];
__device__ __align__(16) float g_kl[BATCH];
__device__ __align__(16) float g_lp[BATCH * 8];   // per-row partial log_px, one per N-block

// ---------------------------------------------------------------------------
// Tiled SGEMM: C[M,N] = A[M,K] @ B[K,N]  (+bias, epilogue variants)
// BM=BN=128, BK=16, 256 threads, 8x8 micro-tile per thread.
// EPI 0: C = relu(acc + bias)
// EPI 1: C = acc + bias
// EPI 2: no C store; lp partial: sum_j -softplus((acc+bias)*(1-2x)) per row,
//        reduced over the 128-col block, written to LP[row*8 + blockIdx.x]
// ---------------------------------------------------------------------------
template <int EPI>
__global__ __launch_bounds__(256)
void gemm_kernel(const float* __restrict__ A, const float* __restrict__ B,
                 const float* __restrict__ bias, float* __restrict__ C,
                 const float* __restrict__ X, float* __restrict__ LP,
                 int N, int K)
{
    __shared__ float As[16][128];       // transposed: As[k][m]
    __shared__ float Bs[16][128];       // Bs[k][n]
    __shared__ float red[128][16];      // row-reduction scratch (EPI 2)

    const int bn   = blockIdx.x;
    const int bm   = blockIdx.y;
    const int tid  = threadIdx.x;
    const int tx   = tid & 15;          // 0..15 -> 8 cols each
    const int ty   = tid >> 4;          // 0..15 -> 8 rows each
    const int row0 = bm * 128;
    const int col0 = bn * 128;

    float acc[8][8];
#pragma unroll
    for (int i = 0; i < 8; i++)
#pragma unroll
        for (int j = 0; j < 8; j++) acc[i][j] = 0.f;

    for (int k0 = 0; k0 < K; k0 += 16) {
#pragma unroll
        for (int l = 0; l < 2; l++) {
            int idx = tid + l * 256;
            // A tile: 128 rows x 16 cols -> 512 float4
            int ra  = idx >> 2;
            int ca  = (idx & 3) * 4;
            float4 va = *(const float4*)&A[(size_t)(row0 + ra) * K + k0 + ca];
            As[ca + 0][ra] = va.x;
            As[ca + 1][ra] = va.y;
            As[ca + 2][ra] = va.z;
            As[ca + 3][ra] = va.w;
            // B tile: 16 rows x 128 cols -> 512 float4
            int rb  = idx >> 5;
            int cb  = (idx & 31) * 4;
            *(float4*)&Bs[rb][cb] = *(const float4*)&B[(size_t)(k0 + rb) * N + col0 + cb];
        }
        __syncthreads();

#pragma unroll
        for (int k = 0; k < 16; k++) {
            float a[8], b[8];
            *(float4*)&a[0] = *(const float4*)&As[k][ty * 8];
            *(float4*)&a[4] = *(const float4*)&As[k][ty * 8 + 4];
            *(float4*)&b[0] = *(const float4*)&Bs[k][tx * 8];
            *(float4*)&b[4] = *(const float4*)&Bs[k][tx * 8 + 4];
#pragma unroll
            for (int i = 0; i < 8; i++)
#pragma unroll
                for (int j = 0; j < 8; j++)
                    acc[i][j] = fmaf(a[i], b[j], acc[i][j]);
        }
        __syncthreads();
    }

    const int crow = row0 + ty * 8;
    const int ccol = col0 + tx * 8;

    if (EPI == 0 || EPI == 1) {
        float bv[8];
#pragma unroll
        for (int j = 0; j < 8; j++) bv[j] = bias[ccol + j];
#pragma unroll
        for (int i = 0; i < 8; i++) {
            float v[8];
#pragma unroll
            for (int j = 0; j < 8; j++) {
                float c = acc[i][j] + bv[j];
                v[j] = (EPI == 0) ? fmaxf(c, 0.f) : c;
            }
            *(float4*)&C[(size_t)(crow + i) * N + ccol]     = *(float4*)&v[0];
            *(float4*)&C[(size_t)(crow + i) * N + ccol + 4] = *(float4*)&v[4];
        }
    } else {
        // EPI 2: Bernoulli log-likelihood partial.
        // lp_elem = x*log(sigmoid(a)) + (1-x)*log(1-sigmoid(a)) = -softplus(t),
        // t = -a if x==1 else a. softplus(t) = max(t,0) + log1p(exp(-|t|)).
        float bv[8];
#pragma unroll
        for (int j = 0; j < 8; j++) bv[j] = bias[ccol + j];
#pragma unroll
        for (int i = 0; i < 8; i++) {
            float s = 0.f;
            float xv[8];
            *(float4*)&xv[0] = *(const float4*)&X[(size_t)(crow + i) * N + ccol];
            *(float4*)&xv[4] = *(const float4*)&X[(size_t)(crow + i) * N + ccol + 4];
#pragma unroll
            for (int j = 0; j < 8; j++) {
                float a = acc[i][j] + bv[j];
                float t = (xv[j] > 0.5f) ? -a : a;
                s -= fmaxf(t, 0.f) + log1pf(expf(-fabsf(t)));
            }
            red[ty * 8 + i][tx] = s;
        }
        __syncthreads();
        if (tid < 128) {
            float s = 0.f;
#pragma unroll
            for (int k = 0; k < 16; k++) s += red[tid][k];
            LP[(size_t)(row0 + tid) * 8 + bn] = s;
        }
    }
}

// ---------------------------------------------------------------------------
// Reparameterization + KL per row: z = mu + exp(ls)*eps,
// kl = 0.5 * sum(exp(2ls) + mu^2 - 2ls - 1)
// one block per row, 128 threads (= LATENT_DIM)
// ---------------------------------------------------------------------------
__global__ void reparam_kernel(const float* __restrict__ mu_, const float* __restrict__ ls_,
                               const float* __restrict__ eps_, float* __restrict__ z_,
                               float* __restrict__ kl_)
{
    const int row = blockIdx.x;
    const int c   = threadIdx.x;
    const int idx = row * D_L + c;
    float m  = mu_[idx];
    float l  = ls_[idx];
    float e  = eps_[idx];
    float sg = expf(l);
    z_[idx]  = fmaf(sg, e, m);
    float t  = 0.5f * (sg * sg + m * m - 2.f * l - 1.f);
#pragma unroll
    for (int off = 16; off > 0; off >>= 1)
        t += __shfl_down_sync(0xffffffffu, t, off);
    __shared__ float w[4];
    if ((c & 31) == 0) w[c >> 5] = t;
    __syncthreads();
    if (c == 0) kl_[row] = w[0] + w[1] + w[2] + w[3];
}

// out[row] = sum_j lp[row][j] - kl[row]
__global__ void finalize_kernel(const float* __restrict__ kl_, const float* __restrict__ lp_,
                                float* __restrict__ out)
{
    int r = blockIdx.x * blockDim.x + threadIdx.x;
    if (r < BATCH) {
        float s = 0.f;
#pragma unroll
        for (int j = 0; j < 8; j++) s += lp_[r * 8 + j];
        out[r] = s - kl_[r];
    }
}

extern "C" void kernel_launch(void* const* d_in, const int* in_sizes, int n_in,
                              void* d_out, int out_size)
{
    const float* x   = (const float*)d_in[0];
    const float* eps = (const float*)d_in[1];
    const float* We1 = (const float*)d_in[2];
    const float* be1 = (const float*)d_in[3];
    const float* Wmu = (const float*)d_in[4];
    const float* bmu = (const float*)d_in[5];
    const float* Wls = (const float*)d_in[6];
    const float* bls = (const float*)d_in[7];
    const float* Wd1 = (const float*)d_in[8];
    const float* bd1 = (const float*)d_in[9];
    const float* Wd2 = (const float*)d_in[10];
    const float* bd2 = (const float*)d_in[11];
    float* out = (float*)d_out;

    float *h, *mu, *ls, *z, *hd, *kl, *lp;
    cudaGetSymbolAddress((void**)&h,  g_h);
    cudaGetSymbolAddress((void**)&mu, g_mu);
    cudaGetSymbolAddress((void**)&ls, g_ls);
    cudaGetSymbolAddress((void**)&z,  g_z);
    cudaGetSymbolAddress((void**)&hd, g_hd);
    cudaGetSymbolAddress((void**)&kl, g_kl);
    cudaGetSymbolAddress((void**)&lp, g_lp);

    // 1) h = relu(x @ We1 + be1)            [32768,1024]
    gemm_kernel<0><<<dim3(D_H / 128, BATCH / 128), 256>>>(x, We1, be1, h, nullptr, nullptr, D_H, D_IN);
    // 2) mu = h @ Wmu + bmu                 [32768,128]
    gemm_kernel<1><<<dim3(1, BATCH / 128), 256>>>(h, Wmu, bmu, mu, nullptr, nullptr, D_L, D_H);
    // 3) ls = h @ Wls + bls                 [32768,128]
    gemm_kernel<1><<<dim3(1, BATCH / 128), 256>>>(h, Wls, bls, ls, nullptr, nullptr, D_L, D_H);
    // 4) z = mu + exp(ls)*eps ; kl per row
    reparam_kernel<<<BATCH, 128>>>(mu, ls, eps, z, kl);
    // 5) hd = relu(z @ Wd1 + bd1)           [32768,1024]
    gemm_kernel<0><<<dim3(D_H / 128, BATCH / 128), 256>>>(z, Wd1, bd1, hd, nullptr, nullptr, D_H, D_L);
    // 6) log_px partials from hd @ Wd2 + bd2, fused Bernoulli log-lik
    gemm_kernel<2><<<dim3(D_IN / 128, BATCH / 128), 256>>>(hd, Wd2, bd2, nullptr, x, lp, D_IN, D_H);
    // 7) out = log_px - kl
    finalize_kernel<<<BATCH / 256, 256>>>(kl, lp, out);
}

// round 3
// speedup vs baseline: 4.3533x; 4.3533x over previous
#include <cuda_runtime.h>
#include <cuda_bf16.h>
#include <cstdint>
#include <math.h>

#define BATCH 32768
#define D_IN  1024
#define D_H   1024
#define D_L   128

// ---------------- scratch (__device__ globals; alloc-free rule) -------------
__device__ __align__(16) __nv_bfloat16 g_xb [BATCH * D_IN];
__device__ __align__(16) __nv_bfloat16 g_hb [BATCH * D_H];
__device__ __align__(16) float         g_ml [BATCH * 256];     // [mu | ls]
__device__ __align__(16) __nv_bfloat16 g_zb [BATCH * D_L];
__device__ __align__(16) __nv_bfloat16 g_hdb[BATCH * D_H];
__device__ __align__(16) float         g_kl [BATCH];
__device__ __align__(16) float         g_lp [BATCH * 16];
__device__ __align__(16) __nv_bfloat16 g_We1t[D_H * D_IN];     // [N][K] K-major
__device__ __align__(16) __nv_bfloat16 g_Wmlt[256 * D_H];
__device__ __align__(16) __nv_bfloat16 g_Wd1t[D_H * D_L];
__device__ __align__(16) __nv_bfloat16 g_Wd2t[D_IN * D_H];
__device__ __align__(16) float         g_bml [256];

// ---------------- helpers ----------------------------------------------------
__device__ __forceinline__ uint32_t smem_u32(const void* p) {
    uint32_t a;
    asm("{ .reg .u64 t; cvta.to.shared.u64 t, %1; cvt.u32.u64 %0, t; }" : "=r"(a) : "l"(p));
    return a;
}

#define CP_ASYNC16(dst, src) \
    asm volatile("cp.async.cg.shared.global [%0], [%1], 16;" :: "r"(dst), "l"(src))
#define CP_COMMIT() asm volatile("cp.async.commit_group;" ::: "memory")
#define CP_WAIT0()  asm volatile("cp.async.wait_group 0;" ::: "memory")
#define CP_WAIT1()  asm volatile("cp.async.wait_group 1;" ::: "memory")
#define CP_WAIT2()  asm volatile("cp.async.wait_group 2;" ::: "memory")

__device__ __forceinline__ void ldsm4(uint32_t& r0, uint32_t& r1, uint32_t& r2, uint32_t& r3,
                                      uint32_t addr) {
    asm volatile("ldmatrix.sync.aligned.m8n8.x4.shared.b16 {%0,%1,%2,%3}, [%4];"
                 : "=r"(r0), "=r"(r1), "=r"(r2), "=r"(r3) : "r"(addr));
}

__device__ __forceinline__ void mma16816(float* c, const uint32_t* a, const uint32_t* b) {
    asm volatile("mma.sync.aligned.m16n8k16.row.col.f32.bf16.bf16.f32 "
                 "{%0,%1,%2,%3}, {%4,%5,%6,%7}, {%8,%9}, {%0,%1,%2,%3};"
                 : "+f"(c[0]), "+f"(c[1]), "+f"(c[2]), "+f"(c[3])
                 : "r"(a[0]), "r"(a[1]), "r"(a[2]), "r"(a[3]), "r"(b[0]), "r"(b[1]));
}

// ---------------- HMMA GEMM: C[M,N] = A[M,K] @ Bt[N,K]^T (+epilogue) ---------
// BM=BN=128, BK=64, 3-stage cp.async pipeline, 8 warps (4m x 2n).
// EPI 0: bf16 relu(acc+bias)   EPI 1: f32 acc+bias
// EPI 2: Bernoulli partial -> LP[row*16 + bn*2 + wn]
static constexpr int STAGE_BYTES = 32768;               // 16KB A + 16KB B
static constexpr int SMEM_SZ = 3 * STAGE_BYTES + 256;

template<int EPI>
__global__ __launch_bounds__(256)
void mma_gemm(const __nv_bfloat16* __restrict__ A, int lda,
              const __nv_bfloat16* __restrict__ Bt,
              const float* __restrict__ bias,
              void* __restrict__ Cv, int ldc,
              const __nv_bfloat16* __restrict__ XB,
              float* __restrict__ LP, int K)
{
    extern __shared__ char smraw[];
    uint32_t raw = smem_u32(smraw);
    uint32_t sbase = (raw + 127u) & ~127u;

    const int tid  = threadIdx.x, lane = tid & 31, wid = tid >> 5;
    const int wm   = wid & 3, wn = wid >> 2;
    const int bn   = blockIdx.x;
    const int m0   = blockIdx.y * 128, col0 = bn * 128;

    const __nv_bfloat16* Ag = A  + (size_t)m0  * lda;
    const __nv_bfloat16* Bg = Bt + (size_t)col0 * K;

    const int T = K >> 6;
    const int P = T < 3 ? T : 3;

    float acc[2][8][4];
#pragma unroll
    for (int mt = 0; mt < 2; ++mt)
#pragma unroll
        for (int nt = 0; nt < 8; ++nt)
#pragma unroll
            for (int q = 0; q < 4; ++q) acc[mt][nt][q] = 0.f;

    // prologue
    for (int kt = 0; kt < P; ++kt) {
        uint32_t sA = sbase + (uint32_t)(kt % 3) * STAGE_BYTES;
        uint32_t sB = sA + 16384u;
        const __nv_bfloat16* Ak = Ag + kt * 64;
        const __nv_bfloat16* Bk = Bg + kt * 64;
#pragma unroll
        for (int i = 0; i < 4; ++i) {
            int idx = tid + i * 256;
            int rr = idx >> 3, cc = idx & 7;
            uint32_t sw = (uint32_t)(rr * 128 + ((cc ^ (rr & 7)) << 4));
            CP_ASYNC16(sA + sw, Ak + (size_t)rr * lda + cc * 8);
            CP_ASYNC16(sB + sw, Bk + (size_t)rr * K   + cc * 8);
        }
        CP_COMMIT();
    }
    int committed = P;

    for (int t = 0; t < T; ++t) {
        int allow = committed - t - 1;
        if (allow >= 2) { CP_WAIT2(); } else if (allow == 1) { CP_WAIT1(); } else { CP_WAIT0(); }
        __syncthreads();

        uint32_t sA = sbase + (uint32_t)(t % 3) * STAGE_BYTES;
        uint32_t sB = sA + 16384u;
        const int g = lane >> 3, lq = lane & 7;

#pragma unroll
        for (int kk = 0; kk < 4; ++kk) {
            uint32_t a[2][4];
#pragma unroll
            for (int mt = 0; mt < 2; ++mt) {
                int row = wm * 32 + mt * 16 + (g & 1) * 8 + lq;
                int kc  = kk * 2 + (g >> 1);
                uint32_t ad = sA + (uint32_t)(row * 128 + ((kc ^ (row & 7)) << 4));
                ldsm4(a[mt][0], a[mt][1], a[mt][2], a[mt][3], ad);
            }
            uint32_t b[8][2];
#pragma unroll
            for (int p = 0; p < 4; ++p) {
                int row = wn * 64 + (p * 2 + (g >> 1)) * 8 + lq;
                int kc  = kk * 2 + (g & 1);
                uint32_t ad = sB + (uint32_t)(row * 128 + ((kc ^ (row & 7)) << 4));
                uint32_t r0, r1, r2, r3;
                ldsm4(r0, r1, r2, r3, ad);
                b[p * 2][0] = r0; b[p * 2][1] = r1;
                b[p * 2 + 1][0] = r2; b[p * 2 + 1][1] = r3;
            }
#pragma unroll
            for (int mt = 0; mt < 2; ++mt)
#pragma unroll
                for (int nt = 0; nt < 8; ++nt)
                    mma16816(acc[mt][nt], a[mt], b[nt]);
        }
        __syncthreads();

        if (t + P < T) {
            int kt = t + P;
            uint32_t nA = sbase + (uint32_t)(kt % 3) * STAGE_BYTES;
            uint32_t nB = nA + 16384u;
            const __nv_bfloat16* Ak = Ag + kt * 64;
            const __nv_bfloat16* Bk = Bg + kt * 64;
#pragma unroll
            for (int i = 0; i < 4; ++i) {
                int idx = tid + i * 256;
                int rr = idx >> 3, cc = idx & 7;
                uint32_t sw = (uint32_t)(rr * 128 + ((cc ^ (rr & 7)) << 4));
                CP_ASYNC16(nA + sw, Ak + (size_t)rr * lda + cc * 8);
                CP_ASYNC16(nB + sw, Bk + (size_t)rr * K   + cc * 8);
            }
            CP_COMMIT();
            committed++;
        }
    }

    // ---------------- epilogue ----------------
    const int rbase = m0 + wm * 32 + (lane >> 2);
    const int cq    = (lane & 3) * 2;

    if (EPI == 0) {
        __nv_bfloat16* C = (__nv_bfloat16*)Cv;
#pragma unroll
        for (int mt = 0; mt < 2; ++mt) {
            int r0 = rbase + mt * 16;
#pragma unroll
            for (int nt = 0; nt < 8; ++nt) {
                int col = col0 + wn * 64 + nt * 8 + cq;
                float b0 = __ldg(bias + col), b1 = __ldg(bias + col + 1);
                float v0 = fmaxf(acc[mt][nt][0] + b0, 0.f);
                float v1 = fmaxf(acc[mt][nt][1] + b1, 0.f);
                float v2 = fmaxf(acc[mt][nt][2] + b0, 0.f);
                float v3 = fmaxf(acc[mt][nt][3] + b1, 0.f);
                __nv_bfloat162 p0 = __float22bfloat162_rn(make_float2(v0, v1));
                __nv_bfloat162 p1 = __float22bfloat162_rn(make_float2(v2, v3));
                *(uint32_t*)(C + (size_t)r0 * ldc + col)       = *(uint32_t*)&p0;
                *(uint32_t*)(C + (size_t)(r0 + 8) * ldc + col) = *(uint32_t*)&p1;
            }
        }
    } else if (EPI == 1) {
        float* C = (float*)Cv;
#pragma unroll
        for (int mt = 0; mt < 2; ++mt) {
            int r0 = rbase + mt * 16;
#pragma unroll
            for (int nt = 0; nt < 8; ++nt) {
                int col = col0 + wn * 64 + nt * 8 + cq;
                float b0 = __ldg(bias + col), b1 = __ldg(bias + col + 1);
                float2 v0 = make_float2(acc[mt][nt][0] + b0, acc[mt][nt][1] + b1);
                float2 v1 = make_float2(acc[mt][nt][2] + b0, acc[mt][nt][3] + b1);
                *(float2*)(C + (size_t)r0 * ldc + col)       = v0;
                *(float2*)(C + (size_t)(r0 + 8) * ldc + col) = v1;
            }
        }
    } else {
#pragma unroll
        for (int mt = 0; mt < 2; ++mt) {
            int r0 = rbase + mt * 16;
            float s0 = 0.f, s1 = 0.f;
#pragma unroll
            for (int nt = 0; nt < 8; ++nt) {
                int col = col0 + wn * 64 + nt * 8 + cq;
                float b0 = __ldg(bias + col), b1 = __ldg(bias + col + 1);
                uint32_t xw0 = *(const uint32_t*)(XB + (size_t)r0 * D_IN + col);
                uint32_t xw1 = *(const uint32_t*)(XB + (size_t)(r0 + 8) * D_IN + col);
                __nv_bfloat162 xp0 = *(__nv_bfloat162*)&xw0;
                __nv_bfloat162 xp1 = *(__nv_bfloat162*)&xw1;
                float a0 = acc[mt][nt][0] + b0, a1 = acc[mt][nt][1] + b1;
                float a2 = acc[mt][nt][2] + b0, a3 = acc[mt][nt][3] + b1;
                float t0 = (__bfloat162float(xp0.x) > 0.5f) ? -a0 : a0;
                float t1 = (__bfloat162float(xp0.y) > 0.5f) ? -a1 : a1;
                float t2 = (__bfloat162float(xp1.x) > 0.5f) ? -a2 : a2;
                float t3 = (__bfloat162float(xp1.y) > 0.5f) ? -a3 : a3;
                s0 += fmaxf(t0, 0.f) + log1pf(__expf(-fabsf(t0)));
                s0 += fmaxf(t1, 0.f) + log1pf(__expf(-fabsf(t1)));
                s1 += fmaxf(t2, 0.f) + log1pf(__expf(-fabsf(t2)));
                s1 += fmaxf(t3, 0.f) + log1pf(__expf(-fabsf(t3)));
            }
            s0 += __shfl_xor_sync(0xffffffffu, s0, 1);
            s0 += __shfl_xor_sync(0xffffffffu, s0, 2);
            s1 += __shfl_xor_sync(0xffffffffu, s1, 1);
            s1 += __shfl_xor_sync(0xffffffffu, s1, 2);
            if ((lane & 3) == 0) {
                LP[(size_t)r0 * 16 + bn * 2 + wn]       = -s0;
                LP[(size_t)(r0 + 8) * 16 + bn * 2 + wn] = -s1;
            }
        }
    }
}

// ---------------- prep / elementwise kernels ---------------------------------
__global__ void convert_x(const float* __restrict__ in, __nv_bfloat16* __restrict__ out) {
    size_t i = ((size_t)blockIdx.x * 256 + threadIdx.x) * 8;
    float4 a = *(const float4*)(in + i);
    float4 b = *(const float4*)(in + i + 4);
    __nv_bfloat162 p[4];
    p[0] = __float22bfloat162_rn(make_float2(a.x, a.y));
    p[1] = __float22bfloat162_rn(make_float2(a.z, a.w));
    p[2] = __float22bfloat162_rn(make_float2(b.x, b.y));
    p[3] = __float22bfloat162_rn(make_float2(b.z, b.w));
    *(int4*)(out + i) = *(int4*)p;
}

// out[(rowOff+n)*K + k] = (bf16) in[k*N + n]
__global__ void transpose_conv(const float* __restrict__ in, __nv_bfloat16* __restrict__ out,
                               int K, int N, int rowOff) {
    __shared__ float t[32][33];
    int k0 = blockIdx.y * 32, n0 = blockIdx.x * 32;
    for (int j = threadIdx.y; j < 32; j += 8)
        t[j][threadIdx.x] = in[(size_t)(k0 + j) * N + n0 + threadIdx.x];
    __syncthreads();
    for (int j = threadIdx.y; j < 32; j += 8)
        out[(size_t)(rowOff + n0 + j) * K + k0 + threadIdx.x] = __float2bfloat16(t[threadIdx.x][j]);
}

__global__ void bias_cat(const float* __restrict__ bmu, const float* __restrict__ bls,
                         float* __restrict__ bml) {
    int i = threadIdx.x;
    bml[i] = (i < 128) ? bmu[i] : bls[i - 128];
}

__global__ void reparam_kernel(const float* __restrict__ ml, const float* __restrict__ eps_,
                               __nv_bfloat16* __restrict__ zb, float* __restrict__ kl_) {
    const int row = blockIdx.x, c = threadIdx.x;
    float m = ml[(size_t)row * 256 + c];
    float l = ml[(size_t)row * 256 + 128 + c];
    float e = eps_[(size_t)row * 128 + c];
    float sg = expf(l);
    zb[(size_t)row * 128 + c] = __float2bfloat16(fmaf(sg, e, m));
    float t = 0.5f * (sg * sg + m * m - 2.f * l - 1.f);
#pragma unroll
    for (int off = 16; off > 0; off >>= 1)
        t += __shfl_down_sync(0xffffffffu, t, off);
    __shared__ float w[4];
    if ((c & 31) == 0) w[c >> 5] = t;
    __syncthreads();
    if (c == 0) kl_[row] = w[0] + w[1] + w[2] + w[3];
}

__global__ void finalize_kernel(const float* __restrict__ kl_, const float* __restrict__ lp_,
                                float* __restrict__ out) {
    int r = blockIdx.x * blockDim.x + threadIdx.x;
    float s = 0.f;
#pragma unroll
    for (int j = 0; j < 16; j++) s += lp_[(size_t)r * 16 + j];
    out[r] = s - kl_[r];
}

// ---------------- launch ------------------------------------------------------
extern "C" void kernel_launch(void* const* d_in, const int* in_sizes, int n_in,
                              void* d_out, int out_size)
{
    const float* x   = (const float*)d_in[0];
    const float* eps = (const float*)d_in[1];
    const float* We1 = (const float*)d_in[2];
    const float* be1 = (const float*)d_in[3];
    const float* Wmu = (const float*)d_in[4];
    const float* bmu = (const float*)d_in[5];
    const float* Wls = (const float*)d_in[6];
    const float* bls = (const float*)d_in[7];
    const float* Wd1 = (const float*)d_in[8];
    const float* bd1 = (const float*)d_in[9];
    const float* Wd2 = (const float*)d_in[10];
    const float* bd2 = (const float*)d_in[11];
    float* out = (float*)d_out;

    __nv_bfloat16 *xb, *hb, *zb, *hdb, *We1t, *Wmlt, *Wd1t, *Wd2t;
    float *ml, *kl, *lp, *bml;
    cudaGetSymbolAddress((void**)&xb,   g_xb);
    cudaGetSymbolAddress((void**)&hb,   g_hb);
    cudaGetSymbolAddress((void**)&ml,   g_ml);
    cudaGetSymbolAddress((void**)&zb,   g_zb);
    cudaGetSymbolAddress((void**)&hdb,  g_hdb);
    cudaGetSymbolAddress((void**)&kl,   g_kl);
    cudaGetSymbolAddress((void**)&lp,   g_lp);
    cudaGetSymbolAddress((void**)&We1t, g_We1t);
    cudaGetSymbolAddress((void**)&Wmlt, g_Wmlt);
    cudaGetSymbolAddress((void**)&Wd1t, g_Wd1t);
    cudaGetSymbolAddress((void**)&Wd2t, g_Wd2t);
    cudaGetSymbolAddress((void**)&bml,  g_bml);

    cudaFuncSetAttribute(mma_gemm<0>, cudaFuncAttributeMaxDynamicSharedMemorySize, SMEM_SZ);
    cudaFuncSetAttribute(mma_gemm<1>, cudaFuncAttributeMaxDynamicSharedMemorySize, SMEM_SZ);
    cudaFuncSetAttribute(mma_gemm<2>, cudaFuncAttributeMaxDynamicSharedMemorySize, SMEM_SZ);

    // prep
    convert_x<<<(BATCH * D_IN) / (256 * 8), 256>>>(x, xb);
    transpose_conv<<<dim3(32, 32), dim3(32, 8)>>>(We1, We1t, D_IN, D_H, 0);
    transpose_conv<<<dim3(4, 32),  dim3(32, 8)>>>(Wmu, Wmlt, D_H, D_L, 0);
    transpose_conv<<<dim3(4, 32),  dim3(32, 8)>>>(Wls, Wmlt, D_H, D_L, 128);
    transpose_conv<<<dim3(32, 4),  dim3(32, 8)>>>(Wd1, Wd1t, D_L, D_H, 0);
    transpose_conv<<<dim3(32, 32), dim3(32, 8)>>>(Wd2, Wd2t, D_H, D_IN, 0);
    bias_cat<<<1, 256>>>(bmu, bls, bml);

    // 1) h = relu(x @ We1 + be1) -> bf16
    mma_gemm<0><<<dim3(8, 256), 256, SMEM_SZ>>>(xb, D_IN, We1t, be1, hb, D_H, nullptr, nullptr, D_IN);
    // 2) [mu|ls] = h @ [Wmu|Wls] + [bmu|bls] -> f32
    mma_gemm<1><<<dim3(2, 256), 256, SMEM_SZ>>>(hb, D_H, Wmlt, bml, ml, 256, nullptr, nullptr, D_H);
    // 3) reparam + KL
    reparam_kernel<<<BATCH, 128>>>(ml, eps, zb, kl);
    // 4) hd = relu(z @ Wd1 + bd1) -> bf16
    mma_gemm<0><<<dim3(8, 256), 256, SMEM_SZ>>>(zb, D_L, Wd1t, bd1, hdb, D_H, nullptr, nullptr, D_L);
    // 5) Bernoulli log-lik partials from hd @ Wd2 + bd2
    mma_gemm<2><<<dim3(8, 256), 256, SMEM_SZ>>>(hdb, D_H, Wd2t, bd2, nullptr, 0, xb, lp, D_H);
    // 6) out = log_px - kl
    finalize_kernel<<<BATCH / 256, 256>>>(kl, lp, out);
}

// round 4
// speedup vs baseline: 6.3283x; 1.4537x over previous
#include <cuda_runtime.h>
#include <cuda_bf16.h>
#include <cstdint>
#include <math.h>

#define BATCH 32768
#define D_IN  1024
#define D_H   1024
#define D_L   128

// ---------------- scratch (__device__ globals; alloc-free rule) -------------
__device__ __align__(16) __nv_bfloat16 g_xb [BATCH * D_IN];
__device__ __align__(16) __nv_bfloat16 g_hb [BATCH * D_H];
__device__ __align__(16) float         g_ml [BATCH * 256];     // [mu | ls]
__device__ __align__(16) __nv_bfloat16 g_zb [BATCH * D_L];
__device__ __align__(16) __nv_bfloat16 g_hdb[BATCH * D_H];
__device__ __align__(16) float         g_kl [BATCH];
__device__ __align__(16) float         g_lp [BATCH * 16];
__device__ __align__(16) __nv_bfloat16 g_We1t[D_H * D_IN];     // [N][K] K-major
__device__ __align__(16) __nv_bfloat16 g_Wmlt[256 * D_H];
__device__ __align__(16) __nv_bfloat16 g_Wd1t[D_H * D_L];
__device__ __align__(16) __nv_bfloat16 g_Wd2t[D_IN * D_H];
__device__ __align__(16) float         g_bml [256];

// ---------------- helpers ----------------------------------------------------
__device__ __forceinline__ uint32_t smem_u32(const void* p) {
    uint32_t a;
    asm("{ .reg .u64 t; cvta.to.shared.u64 t, %1; cvt.u32.u64 %0, t; }" : "=r"(a) : "l"(p));
    return a;
}

#define CP_ASYNC16(dst, src) \
    asm volatile("cp.async.cg.shared.global [%0], [%1], 16;" :: "r"(dst), "l"(src))
#define CP_COMMIT() asm volatile("cp.async.commit_group;" ::: "memory")
#define CP_WAIT0()  asm volatile("cp.async.wait_group 0;" ::: "memory")
#define CP_WAIT1()  asm volatile("cp.async.wait_group 1;" ::: "memory")
#define CP_WAIT2()  asm volatile("cp.async.wait_group 2;" ::: "memory")

__device__ __forceinline__ void ldsm4(uint32_t& r0, uint32_t& r1, uint32_t& r2, uint32_t& r3,
                                      uint32_t addr) {
    asm volatile("ldmatrix.sync.aligned.m8n8.x4.shared.b16 {%0,%1,%2,%3}, [%4];"
                 : "=r"(r0), "=r"(r1), "=r"(r2), "=r"(r3) : "r"(addr));
}

__device__ __forceinline__ void mma16816(float* c, const uint32_t* a, const uint32_t* b) {
    asm volatile("mma.sync.aligned.m16n8k16.row.col.f32.bf16.bf16.f32 "
                 "{%0,%1,%2,%3}, {%4,%5,%6,%7}, {%8,%9}, {%0,%1,%2,%3};"
                 : "+f"(c[0]), "+f"(c[1]), "+f"(c[2]), "+f"(c[3])
                 : "r"(a[0]), "r"(a[1]), "r"(a[2]), "r"(a[3]), "r"(b[0]), "r"(b[1]));
}

// ---------------- HMMA GEMM: C[M,N] = A[M,K] @ Bt[N,K]^T (+epilogue) ---------
// BM=256, BN=128, BK=64. 4-stage cp.async pipeline, ONE __syncthreads/chunk.
// 8 warps (4m x 2n), warp tile 64x64 (acc[4][8][4]).
// EPI 0: bf16 relu(acc+bias)   EPI 1: f32 acc+bias
// EPI 2: Bernoulli partial -> LP[row*16 + bn*2 + wn]
static constexpr int A_BYTES = 256 * 64 * 2;            // 32KB
static constexpr int B_BYTES = 128 * 64 * 2;            // 16KB
static constexpr int STAGE_BYTES = A_BYTES + B_BYTES;   // 48KB
static constexpr int NSTAGE = 4;
static constexpr int SMEM_SZ = NSTAGE * STAGE_BYTES + 128;

template<int EPI>
__global__ __launch_bounds__(256, 1)
void mma_gemm(const __nv_bfloat16* __restrict__ A, int lda,
              const __nv_bfloat16* __restrict__ Bt,
              const float* __restrict__ bias,
              void* __restrict__ Cv, int ldc,
              const __nv_bfloat16* __restrict__ XB,
              float* __restrict__ LP, int K)
{
    extern __shared__ char smraw[];
    uint32_t raw = smem_u32(smraw);
    uint32_t sbase = (raw + 127u) & ~127u;

    const int tid  = threadIdx.x, lane = tid & 31, wid = tid >> 5;
    const int wm   = wid & 3, wn = wid >> 2;
    const int bn   = blockIdx.x;
    const int m0   = blockIdx.y * 256, col0 = bn * 128;

    const __nv_bfloat16* Ag = A  + (size_t)m0   * lda;
    const __nv_bfloat16* Bg = Bt + (size_t)col0 * K;

    const int T = K >> 6;
    const int P = (T < NSTAGE - 1) ? T : (NSTAGE - 1);

    float acc[4][8][4];
#pragma unroll
    for (int mt = 0; mt < 4; ++mt)
#pragma unroll
        for (int nt = 0; nt < 8; ++nt)
#pragma unroll
            for (int q = 0; q < 4; ++q) acc[mt][nt][q] = 0.f;

    // stage loader
    auto issue_stage = [&](int kt) {
        uint32_t sA = sbase + (uint32_t)(kt & 3) * STAGE_BYTES;
        uint32_t sB = sA + A_BYTES;
        const __nv_bfloat16* Ak = Ag + kt * 64;
        const __nv_bfloat16* Bk = Bg + kt * 64;
#pragma unroll
        for (int i = 0; i < 8; ++i) {             // A: 256x64 -> 2048 x16B
            int idx = tid + i * 256;
            int rr = idx >> 3, cc = idx & 7;
            uint32_t sw = (uint32_t)(rr * 128 + ((cc ^ (rr & 7)) << 4));
            CP_ASYNC16(sA + sw, Ak + (size_t)rr * lda + cc * 8);
        }
#pragma unroll
        for (int i = 0; i < 4; ++i) {             // B: 128x64 -> 1024 x16B
            int idx = tid + i * 256;
            int rr = idx >> 3, cc = idx & 7;
            uint32_t sw = (uint32_t)(rr * 128 + ((cc ^ (rr & 7)) << 4));
            CP_ASYNC16(sB + sw, Bk + (size_t)rr * K + cc * 8);
        }
        CP_COMMIT();
    };

    for (int kt = 0; kt < P; ++kt) issue_stage(kt);
    int committed = P;

    const int g = lane >> 3, lq = lane & 7;

    for (int t = 0; t < T; ++t) {
        int allow = committed - t - 1;
        if (allow >= 2) { CP_WAIT2(); } else if (allow == 1) { CP_WAIT1(); } else { CP_WAIT0(); }
        __syncthreads();

        // issue stage t+NSTAGE-1 into buffer (t-1)%4 (fully consumed, sync passed)
        if (t + NSTAGE - 1 < T) { issue_stage(t + NSTAGE - 1); committed++; }

        uint32_t sA = sbase + (uint32_t)(t & 3) * STAGE_BYTES;
        uint32_t sB = sA + A_BYTES;

#pragma unroll
        for (int kk = 0; kk < 4; ++kk) {
            uint32_t a[4][4];
#pragma unroll
            for (int mt = 0; mt < 4; ++mt) {
                int row = wm * 64 + mt * 16 + (g & 1) * 8 + lq;
                int kc  = kk * 2 + (g >> 1);
                uint32_t ad = sA + (uint32_t)(row * 128 + ((kc ^ (row & 7)) << 4));
                ldsm4(a[mt][0], a[mt][1], a[mt][2], a[mt][3], ad);
            }
            uint32_t b[8][2];
#pragma unroll
            for (int p = 0; p < 4; ++p) {
                int row = wn * 64 + (p * 2 + (g >> 1)) * 8 + lq;
                int kc  = kk * 2 + (g & 1);
                uint32_t ad = sB + (uint32_t)(row * 128 + ((kc ^ (row & 7)) << 4));
                uint32_t r0, r1, r2, r3;
                ldsm4(r0, r1, r2, r3, ad);
                b[p * 2][0] = r0; b[p * 2][1] = r1;
                b[p * 2 + 1][0] = r2; b[p * 2 + 1][1] = r3;
            }
#pragma unroll
            for (int mt = 0; mt < 4; ++mt)
#pragma unroll
                for (int nt = 0; nt < 8; ++nt)
                    mma16816(acc[mt][nt], a[mt], b[nt]);
        }
    }

    // ---------------- epilogue ----------------
    const int rbase = m0 + wm * 64 + (lane >> 2);
    const int cq    = (lane & 3) * 2;

    if (EPI == 0) {
        __nv_bfloat16* C = (__nv_bfloat16*)Cv;
#pragma unroll
        for (int mt = 0; mt < 4; ++mt) {
            int r0 = rbase + mt * 16;
#pragma unroll
            for (int nt = 0; nt < 8; ++nt) {
                int col = col0 + wn * 64 + nt * 8 + cq;
                float b0 = __ldg(bias + col), b1 = __ldg(bias + col + 1);
                float v0 = fmaxf(acc[mt][nt][0] + b0, 0.f);
                float v1 = fmaxf(acc[mt][nt][1] + b1, 0.f);
                float v2 = fmaxf(acc[mt][nt][2] + b0, 0.f);
                float v3 = fmaxf(acc[mt][nt][3] + b1, 0.f);
                __nv_bfloat162 p0 = __float22bfloat162_rn(make_float2(v0, v1));
                __nv_bfloat162 p1 = __float22bfloat162_rn(make_float2(v2, v3));
                *(uint32_t*)(C + (size_t)r0 * ldc + col)       = *(uint32_t*)&p0;
                *(uint32_t*)(C + (size_t)(r0 + 8) * ldc + col) = *(uint32_t*)&p1;
            }
        }
    } else if (EPI == 1) {
        float* C = (float*)Cv;
#pragma unroll
        for (int mt = 0; mt < 4; ++mt) {
            int r0 = rbase + mt * 16;
#pragma unroll
            for (int nt = 0; nt < 8; ++nt) {
                int col = col0 + wn * 64 + nt * 8 + cq;
                float b0 = __ldg(bias + col), b1 = __ldg(bias + col + 1);
                float2 v0 = make_float2(acc[mt][nt][0] + b0, acc[mt][nt][1] + b1);
                float2 v1 = make_float2(acc[mt][nt][2] + b0, acc[mt][nt][3] + b1);
                *(float2*)(C + (size_t)r0 * ldc + col)       = v0;
                *(float2*)(C + (size_t)(r0 + 8) * ldc + col) = v1;
            }
        }
    } else {
#pragma unroll
        for (int mt = 0; mt < 4; ++mt) {
            int r0 = rbase + mt * 16;
            float s0 = 0.f, s1 = 0.f;
#pragma unroll
            for (int nt = 0; nt < 8; ++nt) {
                int col = col0 + wn * 64 + nt * 8 + cq;
                float b0 = __ldg(bias + col), b1 = __ldg(bias + col + 1);
                uint32_t xw0 = *(const uint32_t*)(XB + (size_t)r0 * D_IN + col);
                uint32_t xw1 = *(const uint32_t*)(XB + (size_t)(r0 + 8) * D_IN + col);
                __nv_bfloat162 xp0 = *(__nv_bfloat162*)&xw0;
                __nv_bfloat162 xp1 = *(__nv_bfloat162*)&xw1;
                float a0 = acc[mt][nt][0] + b0, a1 = acc[mt][nt][1] + b1;
                float a2 = acc[mt][nt][2] + b0, a3 = acc[mt][nt][3] + b1;
                float t0 = (__bfloat162float(xp0.x) > 0.5f) ? -a0 : a0;
                float t1 = (__bfloat162float(xp0.y) > 0.5f) ? -a1 : a1;
                float t2 = (__bfloat162float(xp1.x) > 0.5f) ? -a2 : a2;
                float t3 = (__bfloat162float(xp1.y) > 0.5f) ? -a3 : a3;
                s0 += fmaxf(t0, 0.f) + log1pf(__expf(-fabsf(t0)));
                s0 += fmaxf(t1, 0.f) + log1pf(__expf(-fabsf(t1)));
                s1 += fmaxf(t2, 0.f) + log1pf(__expf(-fabsf(t2)));
                s1 += fmaxf(t3, 0.f) + log1pf(__expf(-fabsf(t3)));
            }
            s0 += __shfl_xor_sync(0xffffffffu, s0, 1);
            s0 += __shfl_xor_sync(0xffffffffu, s0, 2);
            s1 += __shfl_xor_sync(0xffffffffu, s1, 1);
            s1 += __shfl_xor_sync(0xffffffffu, s1, 2);
            if ((lane & 3) == 0) {
                LP[(size_t)r0 * 16 + bn * 2 + wn]       = -s0;
                LP[(size_t)(r0 + 8) * 16 + bn * 2 + wn] = -s1;
            }
        }
    }
}

// ---------------- prep / elementwise kernels ---------------------------------
__global__ void convert_x(const float* __restrict__ in, __nv_bfloat16* __restrict__ out) {
    size_t i = ((size_t)blockIdx.x * 256 + threadIdx.x) * 8;
    float4 a = *(const float4*)(in + i);
    float4 b = *(const float4*)(in + i + 4);
    __nv_bfloat162 p[4];
    p[0] = __float22bfloat162_rn(make_float2(a.x, a.y));
    p[1] = __float22bfloat162_rn(make_float2(a.z, a.w));
    p[2] = __float22bfloat162_rn(make_float2(b.x, b.y));
    p[3] = __float22bfloat162_rn(make_float2(b.z, b.w));
    *(int4*)(out + i) = *(int4*)p;
}

// out[(rowOff+n)*K + k] = (bf16) in[k*N + n]
__global__ void transpose_conv(const float* __restrict__ in, __nv_bfloat16* __restrict__ out,
                               int K, int N, int rowOff) {
    __shared__ float t[32][33];
    int k0 = blockIdx.y * 32, n0 = blockIdx.x * 32;
    for (int j = threadIdx.y; j < 32; j += 8)
        t[j][threadIdx.x] = in[(size_t)(k0 + j) * N + n0 + threadIdx.x];
    __syncthreads();
    for (int j = threadIdx.y; j < 32; j += 8)
        out[(size_t)(rowOff + n0 + j) * K + k0 + threadIdx.x] = __float2bfloat16(t[threadIdx.x][j]);
}

__global__ void bias_cat(const float* __restrict__ bmu, const float* __restrict__ bls,
                         float* __restrict__ bml) {
    int i = threadIdx.x;
    bml[i] = (i < 128) ? bmu[i] : bls[i - 128];
}

__global__ void reparam_kernel(const float* __restrict__ ml, const float* __restrict__ eps_,
                               __nv_bfloat16* __restrict__ zb, float* __restrict__ kl_) {
    const int row = blockIdx.x, c = threadIdx.x;
    float m = ml[(size_t)row * 256 + c];
    float l = ml[(size_t)row * 256 + 128 + c];
    float e = eps_[(size_t)row * 128 + c];
    float sg = expf(l);
    zb[(size_t)row * 128 + c] = __float2bfloat16(fmaf(sg, e, m));
    float t = 0.5f * (sg * sg + m * m - 2.f * l - 1.f);
#pragma unroll
    for (int off = 16; off > 0; off >>= 1)
        t += __shfl_down_sync(0xffffffffu, t, off);
    __shared__ float w[4];
    if ((c & 31) == 0) w[c >> 5] = t;
    __syncthreads();
    if (c == 0) kl_[row] = w[0] + w[1] + w[2] + w[3];
}

__global__ void finalize_kernel(const float* __restrict__ kl_, const float* __restrict__ lp_,
                                float* __restrict__ out) {
    int r = blockIdx.x * blockDim.x + threadIdx.x;
    float s = 0.f;
#pragma unroll
    for (int j = 0; j < 16; j++) s += lp_[(size_t)r * 16 + j];
    out[r] = s - kl_[r];
}

// ---------------- launch ------------------------------------------------------
extern "C" void kernel_launch(void* const* d_in, const int* in_sizes, int n_in,
                              void* d_out, int out_size)
{
    const float* x   = (const float*)d_in[0];
    const float* eps = (const float*)d_in[1];
    const float* We1 = (const float*)d_in[2];
    const float* be1 = (const float*)d_in[3];
    const float* Wmu = (const float*)d_in[4];
    const float* bmu = (const float*)d_in[5];
    const float* Wls = (const float*)d_in[6];
    const float* bls = (const float*)d_in[7];
    const float* Wd1 = (const float*)d_in[8];
    const float* bd1 = (const float*)d_in[9];
    const float* Wd2 = (const float*)d_in[10];
    const float* bd2 = (const float*)d_in[11];
    float* out = (float*)d_out;

    __nv_bfloat16 *xb, *hb, *zb, *hdb, *We1t, *Wmlt, *Wd1t, *Wd2t;
    float *ml, *kl, *lp, *bml;
    cudaGetSymbolAddress((void**)&xb,   g_xb);
    cudaGetSymbolAddress((void**)&hb,   g_hb);
    cudaGetSymbolAddress((void**)&ml,   g_ml);
    cudaGetSymbolAddress((void**)&zb,   g_zb);
    cudaGetSymbolAddress((void**)&hdb,  g_hdb);
    cudaGetSymbolAddress((void**)&kl,   g_kl);
    cudaGetSymbolAddress((void**)&lp,   g_lp);
    cudaGetSymbolAddress((void**)&We1t, g_We1t);
    cudaGetSymbolAddress((void**)&Wmlt, g_Wmlt);
    cudaGetSymbolAddress((void**)&Wd1t, g_Wd1t);
    cudaGetSymbolAddress((void**)&Wd2t, g_Wd2t);
    cudaGetSymbolAddress((void**)&bml,  g_bml);

    cudaFuncSetAttribute(mma_gemm<0>, cudaFuncAttributeMaxDynamicSharedMemorySize, SMEM_SZ);
    cudaFuncSetAttribute(mma_gemm<1>, cudaFuncAttributeMaxDynamicSharedMemorySize, SMEM_SZ);
    cudaFuncSetAttribute(mma_gemm<2>, cudaFuncAttributeMaxDynamicSharedMemorySize, SMEM_SZ);

    // prep
    convert_x<<<(BATCH * D_IN) / (256 * 8), 256>>>(x, xb);
    transpose_conv<<<dim3(32, 32), dim3(32, 8)>>>(We1, We1t, D_IN, D_H, 0);
    transpose_conv<<<dim3(4, 32),  dim3(32, 8)>>>(Wmu, Wmlt, D_H, D_L, 0);
    transpose_conv<<<dim3(4, 32),  dim3(32, 8)>>>(Wls, Wmlt, D_H, D_L, 128);
    transpose_conv<<<dim3(32, 4),  dim3(32, 8)>>>(Wd1, Wd1t, D_L, D_H, 0);
    transpose_conv<<<dim3(32, 32), dim3(32, 8)>>>(Wd2, Wd2t, D_H, D_IN, 0);
    bias_cat<<<1, 256>>>(bmu, bls, bml);

    // 1) h = relu(x @ We1 + be1) -> bf16
    mma_gemm<0><<<dim3(8, 128), 256, SMEM_SZ>>>(xb, D_IN, We1t, be1, hb, D_H, nullptr, nullptr, D_IN);
    // 2) [mu|ls] = h @ [Wmu|Wls] + [bmu|bls] -> f32
    mma_gemm<1><<<dim3(2, 128), 256, SMEM_SZ>>>(hb, D_H, Wmlt, bml, ml, 256, nullptr, nullptr, D_H);
    // 3) reparam + KL
    reparam_kernel<<<BATCH, 128>>>(ml, eps, zb, kl);
    // 4) hd = relu(z @ Wd1 + bd1) -> bf16
    mma_gemm<0><<<dim3(8, 128), 256, SMEM_SZ>>>(zb, D_L, Wd1t, bd1, hdb, D_H, nullptr, nullptr, D_L);
    // 5) Bernoulli log-lik partials from hd @ Wd2 + bd2
    mma_gemm<2><<<dim3(8, 128), 256, SMEM_SZ>>>(hdb, D_H, Wd2t, bd2, nullptr, 0, xb, lp, D_H);
    // 6) out = log_px - kl
    finalize_kernel<<<BATCH / 256, 256>>>(kl, lp, out);
}

// round 5
// speedup vs baseline: 6.5464x; 1.0345x over previous
#include <cuda_runtime.h>
#include <cuda_bf16.h>
#include <cstdint>
#include <math.h>

#define BATCH 32768
#define D_IN  1024
#define D_H   1024
#define D_L   128

// ---------------- scratch (__device__ globals; alloc-free rule) -------------
__device__ __align__(16) __nv_bfloat16 g_xb [BATCH * D_IN];
__device__ __align__(16) __nv_bfloat16 g_hb [BATCH * D_H];
__device__ __align__(16) __nv_bfloat16 g_zb [BATCH * D_L];
__device__ __align__(16) __nv_bfloat16 g_hdb[BATCH * D_H];
__device__ __align__(16) float         g_kl [BATCH];
__device__ __align__(16) float         g_lp [BATCH * 16];
__device__ __align__(16) __nv_bfloat16 g_We1t[D_H * D_IN];     // [N][K] K-major
__device__ __align__(16) __nv_bfloat16 g_Wmlt[256 * D_H];
__device__ __align__(16) __nv_bfloat16 g_Wd1t[D_H * D_L];
__device__ __align__(16) __nv_bfloat16 g_Wd2t[D_IN * D_H];
__device__ __align__(16) float         g_bml [256];

// ---------------- helpers ----------------------------------------------------
__device__ __forceinline__ uint32_t smem_u32(const void* p) {
    uint32_t a;
    asm("{ .reg .u64 t; cvta.to.shared.u64 t, %1; cvt.u32.u64 %0, t; }" : "=r"(a) : "l"(p));
    return a;
}

#define CP_ASYNC16(dst, src) \
    asm volatile("cp.async.cg.shared.global [%0], [%1], 16;" :: "r"(dst), "l"(src))
#define CP_COMMIT() asm volatile("cp.async.commit_group;" ::: "memory")
#define CP_WAIT0()  asm volatile("cp.async.wait_group 0;" ::: "memory")
#define CP_WAIT1()  asm volatile("cp.async.wait_group 1;" ::: "memory")
#define CP_WAIT2()  asm volatile("cp.async.wait_group 2;" ::: "memory")

__device__ __forceinline__ void ldsm4(uint32_t& r0, uint32_t& r1, uint32_t& r2, uint32_t& r3,
                                      uint32_t addr) {
    asm volatile("ldmatrix.sync.aligned.m8n8.x4.shared.b16 {%0,%1,%2,%3}, [%4];"
                 : "=r"(r0), "=r"(r1), "=r"(r2), "=r"(r3) : "r"(addr));
}

__device__ __forceinline__ void mma16816(float* c, const uint32_t* a, const uint32_t* b) {
    asm volatile("mma.sync.aligned.m16n8k16.row.col.f32.bf16.bf16.f32 "
                 "{%0,%1,%2,%3}, {%4,%5,%6,%7}, {%8,%9}, {%0,%1,%2,%3};"
                 : "+f"(c[0]), "+f"(c[1]), "+f"(c[2]), "+f"(c[3])
                 : "r"(a[0]), "r"(a[1]), "r"(a[2]), "r"(a[3]), "r"(b[0]), "r"(b[1]));
}

// ---------------- HMMA GEMM: C[M,N] = A[M,K] @ Bt[N,K]^T (+epilogue) ---------
// Tile BMxBNx64, 4-stage cp.async pipeline, ONE __syncthreads/chunk.
// 8 warps, warp tile 64x64 (WM=BM/64 x WN=BN/64 warp grid).
// EPI 0: bf16 relu(acc+bias)
// EPI 2: Bernoulli partial -> LP[row*16 + bn*2 + wn]
// EPI 3: fused reparam (BM=128,BN=256): Cv=zb bf16, LP=kl, EPS=eps
static constexpr int NSTAGE = 4;
static constexpr int STAGE_BYTES = (256 + 128) * 64 * 2;       // 48KB (BM+BN=384 both shapes)
static constexpr int SMEM_SZ = NSTAGE * STAGE_BYTES + 128;

template<int EPI, int BM, int BN>
__global__ __launch_bounds__(256, 1)
void mma_gemm(const __nv_bfloat16* __restrict__ A, int lda,
              const __nv_bfloat16* __restrict__ Bt,
              const float* __restrict__ bias,
              void* __restrict__ Cv, int ldc,
              const __nv_bfloat16* __restrict__ XB,
              float* __restrict__ LP,
              const float* __restrict__ EPS, int K)
{
    extern __shared__ char smraw[];
    uint32_t raw = smem_u32(smraw);
    uint32_t sbase = (raw + 127u) & ~127u;

    constexpr int WM = BM / 64, WN = BN / 64;
    constexpr int A_BYTES = BM * 64 * 2;
    constexpr int AI = BM / 32, BI = BN / 32;

    const int tid  = threadIdx.x, lane = tid & 31, wid = tid >> 5;
    const int wm   = wid % WM, wn = wid / WM;
    const int bn   = blockIdx.x;
    const int m0   = blockIdx.y * BM, col0 = bn * BN;

    const __nv_bfloat16* Ag = A  + (size_t)m0   * lda;
    const __nv_bfloat16* Bg = Bt + (size_t)col0 * K;

    const int T = K >> 6;
    const int P = (T < NSTAGE - 1) ? T : (NSTAGE - 1);

    float acc[4][8][4];
#pragma unroll
    for (int mt = 0; mt < 4; ++mt)
#pragma unroll
        for (int nt = 0; nt < 8; ++nt)
#pragma unroll
            for (int q = 0; q < 4; ++q) acc[mt][nt][q] = 0.f;

    auto issue_stage = [&](int kt) {
        uint32_t sA = sbase + (uint32_t)(kt & 3) * STAGE_BYTES;
        uint32_t sB = sA + A_BYTES;
        const __nv_bfloat16* Ak = Ag + kt * 64;
        const __nv_bfloat16* Bk = Bg + kt * 64;
#pragma unroll
        for (int i = 0; i < AI; ++i) {
            int idx = tid + i * 256;
            int rr = idx >> 3, cc = idx & 7;
            uint32_t sw = (uint32_t)(rr * 128 + ((cc ^ (rr & 7)) << 4));
            CP_ASYNC16(sA + sw, Ak + (size_t)rr * lda + cc * 8);
        }
#pragma unroll
        for (int i = 0; i < BI; ++i) {
            int idx = tid + i * 256;
            int rr = idx >> 3, cc = idx & 7;
            uint32_t sw = (uint32_t)(rr * 128 + ((cc ^ (rr & 7)) << 4));
            CP_ASYNC16(sB + sw, Bk + (size_t)rr * K + cc * 8);
        }
        CP_COMMIT();
    };

    for (int kt = 0; kt < P; ++kt) issue_stage(kt);
    int committed = P;

    const int g = lane >> 3, lq = lane & 7;

    for (int t = 0; t < T; ++t) {
        int allow = committed - t - 1;
        if (allow >= 2) { CP_WAIT2(); } else if (allow == 1) { CP_WAIT1(); } else { CP_WAIT0(); }
        __syncthreads();

        if (t + NSTAGE - 1 < T) { issue_stage(t + NSTAGE - 1); committed++; }

        uint32_t sA = sbase + (uint32_t)(t & 3) * STAGE_BYTES;
        uint32_t sB = sA + A_BYTES;

#pragma unroll
        for (int kk = 0; kk < 4; ++kk) {
            uint32_t a[4][4];
#pragma unroll
            for (int mt = 0; mt < 4; ++mt) {
                int row = wm * 64 + mt * 16 + (g & 1) * 8 + lq;
                int kc  = kk * 2 + (g >> 1);
                uint32_t ad = sA + (uint32_t)(row * 128 + ((kc ^ (row & 7)) << 4));
                ldsm4(a[mt][0], a[mt][1], a[mt][2], a[mt][3], ad);
            }
            uint32_t b[8][2];
#pragma unroll
            for (int p = 0; p < 4; ++p) {
                int row = wn * 64 + (p * 2 + (g >> 1)) * 8 + lq;
                int kc  = kk * 2 + (g & 1);
                uint32_t ad = sB + (uint32_t)(row * 128 + ((kc ^ (row & 7)) << 4));
                uint32_t r0, r1, r2, r3;
                ldsm4(r0, r1, r2, r3, ad);
                b[p * 2][0] = r0; b[p * 2][1] = r1;
                b[p * 2 + 1][0] = r2; b[p * 2 + 1][1] = r3;
            }
#pragma unroll
            for (int mt = 0; mt < 4; ++mt)
#pragma unroll
                for (int nt = 0; nt < 8; ++nt)
                    mma16816(acc[mt][nt], a[mt], b[nt]);
        }
    }

    // ---------------- epilogue ----------------
    const int rbase = m0 + wm * 64 + (lane >> 2);
    const int cq    = (lane & 3) * 2;

    if (EPI == 0) {
        __nv_bfloat16* C = (__nv_bfloat16*)Cv;
#pragma unroll
        for (int mt = 0; mt < 4; ++mt) {
            int r0 = rbase + mt * 16;
#pragma unroll
            for (int nt = 0; nt < 8; ++nt) {
                int col = col0 + wn * 64 + nt * 8 + cq;
                float b0 = __ldg(bias + col), b1 = __ldg(bias + col + 1);
                float v0 = fmaxf(acc[mt][nt][0] + b0, 0.f);
                float v1 = fmaxf(acc[mt][nt][1] + b1, 0.f);
                float v2 = fmaxf(acc[mt][nt][2] + b0, 0.f);
                float v3 = fmaxf(acc[mt][nt][3] + b1, 0.f);
                __nv_bfloat162 p0 = __float22bfloat162_rn(make_float2(v0, v1));
                __nv_bfloat162 p1 = __float22bfloat162_rn(make_float2(v2, v3));
                *(uint32_t*)(C + (size_t)r0 * ldc + col)       = *(uint32_t*)&p0;
                *(uint32_t*)(C + (size_t)(r0 + 8) * ldc + col) = *(uint32_t*)&p1;
            }
        }
    } else if (EPI == 2) {
#pragma unroll
        for (int mt = 0; mt < 4; ++mt) {
            int r0 = rbase + mt * 16;
            float s0 = 0.f, s1 = 0.f;
#pragma unroll
            for (int nt = 0; nt < 8; ++nt) {
                int col = col0 + wn * 64 + nt * 8 + cq;
                float b0 = __ldg(bias + col), b1 = __ldg(bias + col + 1);
                uint32_t xw0 = *(const uint32_t*)(XB + (size_t)r0 * D_IN + col);
                uint32_t xw1 = *(const uint32_t*)(XB + (size_t)(r0 + 8) * D_IN + col);
                __nv_bfloat162 xp0 = *(__nv_bfloat162*)&xw0;
                __nv_bfloat162 xp1 = *(__nv_bfloat162*)&xw1;
                float a0 = acc[mt][nt][0] + b0, a1 = acc[mt][nt][1] + b1;
                float a2 = acc[mt][nt][2] + b0, a3 = acc[mt][nt][3] + b1;
                float t0 = (__bfloat162float(xp0.x) > 0.5f) ? -a0 : a0;
                float t1 = (__bfloat162float(xp0.y) > 0.5f) ? -a1 : a1;
                float t2 = (__bfloat162float(xp1.x) > 0.5f) ? -a2 : a2;
                float t3 = (__bfloat162float(xp1.y) > 0.5f) ? -a3 : a3;
                s0 += fmaxf(t0, 0.f) + log1pf(__expf(-fabsf(t0)));
                s0 += fmaxf(t1, 0.f) + log1pf(__expf(-fabsf(t1)));
                s1 += fmaxf(t2, 0.f) + log1pf(__expf(-fabsf(t2)));
                s1 += fmaxf(t3, 0.f) + log1pf(__expf(-fabsf(t3)));
            }
            s0 += __shfl_xor_sync(0xffffffffu, s0, 1);
            s0 += __shfl_xor_sync(0xffffffffu, s0, 2);
            s1 += __shfl_xor_sync(0xffffffffu, s1, 1);
            s1 += __shfl_xor_sync(0xffffffffu, s1, 2);
            if ((lane & 3) == 0) {
                LP[(size_t)r0 * 16 + bn * 2 + wn]       = -s0;
                LP[(size_t)(r0 + 8) * 16 + bn * 2 + wn] = -s1;
            }
        }
    } else {
        // EPI 3: fused reparam + KL. BM=128, BN=256 (cols 0..127 = mu, 128..255 = ls).
        constexpr int SPAD = 258;                    // padded row stride (floats)
        float* S = (float*)(smraw + (sbase - raw));
        __syncthreads();                             // all warps done with pipeline smem
        const int rl = wm * 64 + (lane >> 2);        // local row 0..127
#pragma unroll
        for (int mt = 0; mt < 4; ++mt) {
            int r0 = rl + mt * 16;
#pragma unroll
            for (int nt = 0; nt < 8; ++nt) {
                int col = wn * 64 + nt * 8 + cq;
                float b0 = __ldg(bias + col), b1 = __ldg(bias + col + 1);
                *(float2*)&S[(size_t)r0 * SPAD + col] =
                    make_float2(acc[mt][nt][0] + b0, acc[mt][nt][1] + b1);
                *(float2*)&S[(size_t)(r0 + 8) * SPAD + col] =
                    make_float2(acc[mt][nt][2] + b0, acc[mt][nt][3] + b1);
            }
        }
        __syncthreads();

        const int r = tid >> 1, h = tid & 1;         // 128 rows x 2 halves
        const size_t grow = (size_t)m0 + r;
        const float* erow = EPS + grow * 128 + h * 64;
        __nv_bfloat16* ZB = (__nv_bfloat16*)Cv;
        float kla = 0.f;
        uint32_t zbuf[32];
#pragma unroll
        for (int j = 0; j < 32; ++j) {
            int c = h * 64 + 2 * j;
            float mu0 = S[(size_t)r * SPAD + c];
            float mu1 = S[(size_t)r * SPAD + c + 1];
            float l0  = S[(size_t)r * SPAD + c + 128];
            float l1  = S[(size_t)r * SPAD + c + 129];
            float2 ep = *(const float2*)&erow[2 * j];
            float s0 = expf(l0), s1 = expf(l1);
            float z0 = fmaf(s0, ep.x, mu0), z1 = fmaf(s1, ep.y, mu1);
            __nv_bfloat162 p = __float22bfloat162_rn(make_float2(z0, z1));
            zbuf[j] = *(uint32_t*)&p;
            kla += s0 * s0 + mu0 * mu0 - 2.f * l0 - 1.f;
            kla += s1 * s1 + mu1 * mu1 - 2.f * l1 - 1.f;
        }
        int4* zo = (int4*)(ZB + grow * 128 + h * 64);
#pragma unroll
        for (int q = 0; q < 8; ++q) zo[q] = ((int4*)zbuf)[q];
        kla += __shfl_xor_sync(0xffffffffu, kla, 1);
        if (h == 0) LP[grow] = 0.5f * kla;           // LP carries kl here
    }
}

// ---------------- fused prep kernel ------------------------------------------
// blocks [0,16384): x -> bf16
// blocks [16384,17408): We1  transpose (grid 32x32)
// blocks [17408,17536): Wmu  transpose (grid 4x32) -> Wmlt rows 0..127
// blocks [17536,17664): Wls  transpose (grid 4x32) -> Wmlt rows 128..255
// blocks [17664,17792): Wd1  transpose (grid 32x4)
// blocks [17792,18816): Wd2  transpose (grid 32x32)
// block  18816: bias concat
__device__ __forceinline__ void do_transpose(float (*ts)[33],
                                             const float* __restrict__ in,
                                             __nv_bfloat16* __restrict__ out,
                                             int K, int N, int rowOff, int bx, int by, int tid) {
    int tx = tid & 31, ty = tid >> 5;
    int k0 = by * 32, n0 = bx * 32;
    for (int j = ty; j < 32; j += 8)
        ts[j][tx] = in[(size_t)(k0 + j) * N + n0 + tx];
    __syncthreads();
    for (int j = ty; j < 32; j += 8)
        out[(size_t)(rowOff + n0 + j) * K + k0 + tx] = __float2bfloat16(ts[tx][j]);
}

__global__ __launch_bounds__(256)
void prep_kernel(const float* __restrict__ x,
                 const float* __restrict__ We1, const float* __restrict__ Wmu,
                 const float* __restrict__ Wls, const float* __restrict__ Wd1,
                 const float* __restrict__ Wd2, const float* __restrict__ bmu,
                 const float* __restrict__ bls,
                 __nv_bfloat16* __restrict__ xb, __nv_bfloat16* __restrict__ We1t,
                 __nv_bfloat16* __restrict__ Wmlt, __nv_bfloat16* __restrict__ Wd1t,
                 __nv_bfloat16* __restrict__ Wd2t, float* __restrict__ bml)
{
    __shared__ float ts[32][33];
    const int b = blockIdx.x, tid = threadIdx.x;
    if (b < 16384) {
        size_t i = ((size_t)b * 256 + tid) * 8;
        float4 a = *(const float4*)(x + i);
        float4 c = *(const float4*)(x + i + 4);
        __nv_bfloat162 p[4];
        p[0] = __float22bfloat162_rn(make_float2(a.x, a.y));
        p[1] = __float22bfloat162_rn(make_float2(a.z, a.w));
        p[2] = __float22bfloat162_rn(make_float2(c.x, c.y));
        p[3] = __float22bfloat162_rn(make_float2(c.z, c.w));
        *(int4*)(xb + i) = *(int4*)p;
    } else if (b < 17408) {
        int r = b - 16384;  do_transpose(ts, We1, We1t, 1024, 1024, 0,   r % 32, r / 32, tid);
    } else if (b < 17536) {
        int r = b - 17408;  do_transpose(ts, Wmu, Wmlt, 1024, 128,  0,   r % 4,  r / 4,  tid);
    } else if (b < 17664) {
        int r = b - 17536;  do_transpose(ts, Wls, Wmlt, 1024, 128,  128, r % 4,  r / 4,  tid);
    } else if (b < 17792) {
        int r = b - 17664;  do_transpose(ts, Wd1, Wd1t, 128,  1024, 0,   r % 32, r / 32, tid);
    } else if (b < 18816) {
        int r = b - 17792;  do_transpose(ts, Wd2, Wd2t, 1024, 1024, 0,   r % 32, r / 32, tid);
    } else {
        bml[tid] = (tid < 128) ? bmu[tid] : bls[tid - 128];
    }
}

__global__ void finalize_kernel(const float* __restrict__ kl_, const float* __restrict__ lp_,
                                float* __restrict__ out) {
    int r = blockIdx.x * blockDim.x + threadIdx.x;
    float s = 0.f;
#pragma unroll
    for (int j = 0; j < 16; j++) s += lp_[(size_t)r * 16 + j];
    out[r] = s - kl_[r];
}

// ---------------- launch ------------------------------------------------------
extern "C" void kernel_launch(void* const* d_in, const int* in_sizes, int n_in,
                              void* d_out, int out_size)
{
    const float* x   = (const float*)d_in[0];
    const float* eps = (const float*)d_in[1];
    const float* We1 = (const float*)d_in[2];
    const float* be1 = (const float*)d_in[3];
    const float* Wmu = (const float*)d_in[4];
    const float* bmu = (const float*)d_in[5];
    const float* Wls = (const float*)d_in[6];
    const float* bls = (const float*)d_in[7];
    const float* Wd1 = (const float*)d_in[8];
    const float* bd1 = (const float*)d_in[9];
    const float* Wd2 = (const float*)d_in[10];
    const float* bd2 = (const float*)d_in[11];
    float* out = (float*)d_out;

    __nv_bfloat16 *xb, *hb, *zb, *hdb, *We1t, *Wmlt, *Wd1t, *Wd2t;
    float *kl, *lp, *bml;
    cudaGetSymbolAddress((void**)&xb,   g_xb);
    cudaGetSymbolAddress((void**)&hb,   g_hb);
    cudaGetSymbolAddress((void**)&zb,   g_zb);
    cudaGetSymbolAddress((void**)&hdb,  g_hdb);
    cudaGetSymbolAddress((void**)&kl,   g_kl);
    cudaGetSymbolAddress((void**)&lp,   g_lp);
    cudaGetSymbolAddress((void**)&We1t, g_We1t);
    cudaGetSymbolAddress((void**)&Wmlt, g_Wmlt);
    cudaGetSymbolAddress((void**)&Wd1t, g_Wd1t);
    cudaGetSymbolAddress((void**)&Wd2t, g_Wd2t);
    cudaGetSymbolAddress((void**)&bml,  g_bml);

    cudaFuncSetAttribute((const void*)mma_gemm<0,256,128>, cudaFuncAttributeMaxDynamicSharedMemorySize, SMEM_SZ);
    cudaFuncSetAttribute((const void*)mma_gemm<2,256,128>, cudaFuncAttributeMaxDynamicSharedMemorySize, SMEM_SZ);
    cudaFuncSetAttribute((const void*)mma_gemm<3,128,256>, cudaFuncAttributeMaxDynamicSharedMemorySize, SMEM_SZ);

    // 0) fused prep: x->bf16, weight transposes, bias concat
    prep_kernel<<<18817, 256>>>(x, We1, Wmu, Wls, Wd1, Wd2, bmu, bls,
                                xb, We1t, Wmlt, Wd1t, Wd2t, bml);
    // 1) h = relu(x @ We1 + be1) -> bf16
    mma_gemm<0,256,128><<<dim3(8, 128), 256, SMEM_SZ>>>(xb, D_IN, We1t, be1, hb, D_H,
                                                        nullptr, nullptr, nullptr, D_IN);
    // 2) [mu|ls] GEMM + fused reparam/KL -> zb (bf16), kl
    mma_gemm<3,128,256><<<dim3(1, 256), 256, SMEM_SZ>>>(hb, D_H, Wmlt, bml, zb, D_L,
                                                        nullptr, kl, eps, D_H);
    // 3) hd = relu(z @ Wd1 + bd1) -> bf16
    mma_gemm<0,256,128><<<dim3(8, 128), 256, SMEM_SZ>>>(zb, D_L, Wd1t, bd1, hdb, D_H,
                                                        nullptr, nullptr, nullptr, D_L);
    // 4) Bernoulli log-lik partials from hd @ Wd2 + bd2
    mma_gemm<2,256,128><<<dim3(8, 128), 256, SMEM_SZ>>>(hdb, D_H, Wd2t, bd2, nullptr, 0,
                                                        xb, lp, nullptr, D_H);
    // 5) out = log_px - kl
    finalize_kernel<<<BATCH / 256, 256>>>(kl, lp, out);
}

// round 6
// speedup vs baseline: 6.6677x; 1.0185x over previous
#include <cuda_runtime.h>
#include <cuda_bf16.h>
#include <cstdint>
#include <math.h>

#define BATCH 32768
#define D_IN  1024
#define D_H   1024
#define D_L   128

// ---------------- scratch (__device__ globals; alloc-free rule) -------------
__device__ __align__(16) __nv_bfloat16 g_xb [BATCH * D_IN];
__device__ __align__(16) __nv_bfloat16 g_hb [BATCH * D_H];
__device__ __align__(16) __nv_bfloat16 g_zb [BATCH * D_L];
__device__ __align__(16) __nv_bfloat16 g_hdb[BATCH * D_H];
__device__ __align__(16) float         g_kl [BATCH];
__device__ __align__(16) float         g_lp [BATCH * 32];
__device__ __align__(16) __nv_bfloat16 g_We1t[D_H * D_IN];     // [N][K] K-major
__device__ __align__(16) __nv_bfloat16 g_Wmlt[256 * D_H];
__device__ __align__(16) __nv_bfloat16 g_Wd1t[D_H * D_L];
__device__ __align__(16) __nv_bfloat16 g_Wd2t[D_IN * D_H];
__device__ __align__(16) float         g_bml [256];

// ---------------- helpers ----------------------------------------------------
__device__ __forceinline__ uint32_t smem_u32(const void* p) {
    uint32_t a;
    asm("{ .reg .u64 t; cvta.to.shared.u64 t, %1; cvt.u32.u64 %0, t; }" : "=r"(a) : "l"(p));
    return a;
}

#define CP_ASYNC16(dst, src) \
    asm volatile("cp.async.cg.shared.global [%0], [%1], 16;" :: "r"(dst), "l"(src))
#define CP_COMMIT() asm volatile("cp.async.commit_group;" ::: "memory")
#define CP_WAIT0()  asm volatile("cp.async.wait_group 0;" ::: "memory")
#define CP_WAIT1()  asm volatile("cp.async.wait_group 1;" ::: "memory")
#define CP_WAIT2()  asm volatile("cp.async.wait_group 2;" ::: "memory")

__device__ __forceinline__ void ldsm4(uint32_t& r0, uint32_t& r1, uint32_t& r2, uint32_t& r3,
                                      uint32_t addr) {
    asm volatile("ldmatrix.sync.aligned.m8n8.x4.shared.b16 {%0,%1,%2,%3}, [%4];"
                 : "=r"(r0), "=r"(r1), "=r"(r2), "=r"(r3) : "r"(addr));
}

__device__ __forceinline__ void mma16816(float* c, const uint32_t* a, const uint32_t* b) {
    asm volatile("mma.sync.aligned.m16n8k16.row.col.f32.bf16.bf16.f32 "
                 "{%0,%1,%2,%3}, {%4,%5,%6,%7}, {%8,%9}, {%0,%1,%2,%3};"
                 : "+f"(c[0]), "+f"(c[1]), "+f"(c[2]), "+f"(c[3])
                 : "r"(a[0]), "r"(a[1]), "r"(a[2]), "r"(a[3]), "r"(b[0]), "r"(b[1]));
}

// ---------------- HMMA GEMM: C[M,N] = A[M,K] @ Bt[N,K]^T (+epilogue) ---------
// Tile BMxBNx64, 4-stage cp.async pipeline, ONE __syncthreads/chunk.
// 512 threads = 16 warps, warp tile 64x32 (WM=BM/64 x WN=BN/32 warp grid).
// EPI 0: bf16 relu(acc+bias)
// EPI 2: Bernoulli partial -> LP[row*32 + bn*4 + wn]
// EPI 3: fused reparam (BM=128,BN=256): Cv=zb bf16, LP=kl, EPS=eps
static constexpr int NSTAGE = 4;
static constexpr int STAGE_BYTES = (256 + 128) * 64 * 2;       // 48KB (BM+BN=384 both shapes)
static constexpr int SMEM_SZ = NSTAGE * STAGE_BYTES + 128;
static constexpr int NTHR = 512;

template<int EPI, int BM, int BN>
__global__ __launch_bounds__(NTHR, 1)
void mma_gemm(const __nv_bfloat16* __restrict__ A, int lda,
              const __nv_bfloat16* __restrict__ Bt,
              const float* __restrict__ bias,
              void* __restrict__ Cv, int ldc,
              const __nv_bfloat16* __restrict__ XB,
              float* __restrict__ LP,
              const float* __restrict__ EPS, int K)
{
    extern __shared__ char smraw[];
    uint32_t raw = smem_u32(smraw);
    uint32_t sbase = (raw + 127u) & ~127u;

    constexpr int WM = BM / 64;            // warp rows
    constexpr int A_BYTES = BM * 64 * 2;
    constexpr int AI = BM / 64, BI = BN / 64;   // loader iters (512 thr, 16B each)

    const int tid  = threadIdx.x, lane = tid & 31, wid = tid >> 5;
    const int wm   = wid % WM, wn = wid / WM;   // wn in [0, BN/32)
    const int bn   = blockIdx.x;
    const int m0   = blockIdx.y * BM, col0 = bn * BN;

    const __nv_bfloat16* Ag = A  + (size_t)m0   * lda;
    const __nv_bfloat16* Bg = Bt + (size_t)col0 * K;

    const int T = K >> 6;
    const int P = (T < NSTAGE - 1) ? T : (NSTAGE - 1);

    float acc[4][4][4];
#pragma unroll
    for (int mt = 0; mt < 4; ++mt)
#pragma unroll
        for (int nt = 0; nt < 4; ++nt)
#pragma unroll
            for (int q = 0; q < 4; ++q) acc[mt][nt][q] = 0.f;

    auto issue_stage = [&](int kt) {
        uint32_t sA = sbase + (uint32_t)(kt & 3) * STAGE_BYTES;
        uint32_t sB = sA + A_BYTES;
        const __nv_bfloat16* Ak = Ag + kt * 64;
        const __nv_bfloat16* Bk = Bg + kt * 64;
#pragma unroll
        for (int i = 0; i < AI; ++i) {
            int idx = tid + i * NTHR;
            int rr = idx >> 3, cc = idx & 7;
            uint32_t sw = (uint32_t)(rr * 128 + ((cc ^ (rr & 7)) << 4));
            CP_ASYNC16(sA + sw, Ak + (size_t)rr * lda + cc * 8);
        }
#pragma unroll
        for (int i = 0; i < BI; ++i) {
            int idx = tid + i * NTHR;
            int rr = idx >> 3, cc = idx & 7;
            uint32_t sw = (uint32_t)(rr * 128 + ((cc ^ (rr & 7)) << 4));
            CP_ASYNC16(sB + sw, Bk + (size_t)rr * K + cc * 8);
        }
        CP_COMMIT();
    };

    for (int kt = 0; kt < P; ++kt) issue_stage(kt);
    int committed = P;

    const int g = lane >> 3, lq = lane & 7;

    for (int t = 0; t < T; ++t) {
        int allow = committed - t - 1;
        if (allow >= 2) { CP_WAIT2(); } else if (allow == 1) { CP_WAIT1(); } else { CP_WAIT0(); }
        __syncthreads();

        if (t + NSTAGE - 1 < T) { issue_stage(t + NSTAGE - 1); committed++; }

        uint32_t sA = sbase + (uint32_t)(t & 3) * STAGE_BYTES;
        uint32_t sB = sA + A_BYTES;

#pragma unroll
        for (int kk = 0; kk < 4; ++kk) {
            uint32_t a[4][4];
#pragma unroll
            for (int mt = 0; mt < 4; ++mt) {
                int row = wm * 64 + mt * 16 + (g & 1) * 8 + lq;
                int kc  = kk * 2 + (g >> 1);
                uint32_t ad = sA + (uint32_t)(row * 128 + ((kc ^ (row & 7)) << 4));
                ldsm4(a[mt][0], a[mt][1], a[mt][2], a[mt][3], ad);
            }
            uint32_t b[4][2];
#pragma unroll
            for (int p = 0; p < 2; ++p) {
                int row = wn * 32 + (p * 2 + (g >> 1)) * 8 + lq;
                int kc  = kk * 2 + (g & 1);
                uint32_t ad = sB + (uint32_t)(row * 128 + ((kc ^ (row & 7)) << 4));
                uint32_t r0, r1, r2, r3;
                ldsm4(r0, r1, r2, r3, ad);
                b[p * 2][0] = r0; b[p * 2][1] = r1;
                b[p * 2 + 1][0] = r2; b[p * 2 + 1][1] = r3;
            }
#pragma unroll
            for (int mt = 0; mt < 4; ++mt)
#pragma unroll
                for (int nt = 0; nt < 4; ++nt)
                    mma16816(acc[mt][nt], a[mt], b[nt]);
        }
    }

    // ---------------- epilogue ----------------
    const int rbase = m0 + wm * 64 + (lane >> 2);
    const int cq    = (lane & 3) * 2;

    if (EPI == 0) {
        __nv_bfloat16* C = (__nv_bfloat16*)Cv;
#pragma unroll
        for (int mt = 0; mt < 4; ++mt) {
            int r0 = rbase + mt * 16;
#pragma unroll
            for (int nt = 0; nt < 4; ++nt) {
                int col = col0 + wn * 32 + nt * 8 + cq;
                float b0 = __ldg(bias + col), b1 = __ldg(bias + col + 1);
                float v0 = fmaxf(acc[mt][nt][0] + b0, 0.f);
                float v1 = fmaxf(acc[mt][nt][1] + b1, 0.f);
                float v2 = fmaxf(acc[mt][nt][2] + b0, 0.f);
                float v3 = fmaxf(acc[mt][nt][3] + b1, 0.f);
                __nv_bfloat162 p0 = __float22bfloat162_rn(make_float2(v0, v1));
                __nv_bfloat162 p1 = __float22bfloat162_rn(make_float2(v2, v3));
                *(uint32_t*)(C + (size_t)r0 * ldc + col)       = *(uint32_t*)&p0;
                *(uint32_t*)(C + (size_t)(r0 + 8) * ldc + col) = *(uint32_t*)&p1;
            }
        }
    } else if (EPI == 2) {
#pragma unroll
        for (int mt = 0; mt < 4; ++mt) {
            int r0 = rbase + mt * 16;
            float s0 = 0.f, s1 = 0.f;
#pragma unroll
            for (int nt = 0; nt < 4; ++nt) {
                int col = col0 + wn * 32 + nt * 8 + cq;
                float b0 = __ldg(bias + col), b1 = __ldg(bias + col + 1);
                uint32_t xw0 = *(const uint32_t*)(XB + (size_t)r0 * D_IN + col);
                uint32_t xw1 = *(const uint32_t*)(XB + (size_t)(r0 + 8) * D_IN + col);
                __nv_bfloat162 xp0 = *(__nv_bfloat162*)&xw0;
                __nv_bfloat162 xp1 = *(__nv_bfloat162*)&xw1;
                float a0 = acc[mt][nt][0] + b0, a1 = acc[mt][nt][1] + b1;
                float a2 = acc[mt][nt][2] + b0, a3 = acc[mt][nt][3] + b1;
                float t0 = (__bfloat162float(xp0.x) > 0.5f) ? -a0 : a0;
                float t1 = (__bfloat162float(xp0.y) > 0.5f) ? -a1 : a1;
                float t2 = (__bfloat162float(xp1.x) > 0.5f) ? -a2 : a2;
                float t3 = (__bfloat162float(xp1.y) > 0.5f) ? -a3 : a3;
                s0 += fmaxf(t0, 0.f) + log1pf(__expf(-fabsf(t0)));
                s0 += fmaxf(t1, 0.f) + log1pf(__expf(-fabsf(t1)));
                s1 += fmaxf(t2, 0.f) + log1pf(__expf(-fabsf(t2)));
                s1 += fmaxf(t3, 0.f) + log1pf(__expf(-fabsf(t3)));
            }
            s0 += __shfl_xor_sync(0xffffffffu, s0, 1);
            s0 += __shfl_xor_sync(0xffffffffu, s0, 2);
            s1 += __shfl_xor_sync(0xffffffffu, s1, 1);
            s1 += __shfl_xor_sync(0xffffffffu, s1, 2);
            if ((lane & 3) == 0) {
                LP[(size_t)r0 * 32 + bn * 4 + wn]       = -s0;
                LP[(size_t)(r0 + 8) * 32 + bn * 4 + wn] = -s1;
            }
        }
    } else {
        // EPI 3: fused reparam + KL. BM=128, BN=256 (cols 0..127 = mu, 128..255 = ls).
        constexpr int SPAD = 258;
        float* S = (float*)(smraw + (sbase - raw));
        __syncthreads();
        const int rl = wm * 64 + (lane >> 2);
#pragma unroll
        for (int mt = 0; mt < 4; ++mt) {
            int r0 = rl + mt * 16;
#pragma unroll
            for (int nt = 0; nt < 4; ++nt) {
                int col = wn * 32 + nt * 8 + cq;
                float b0 = __ldg(bias + col), b1 = __ldg(bias + col + 1);
                *(float2*)&S[(size_t)r0 * SPAD + col] =
                    make_float2(acc[mt][nt][0] + b0, acc[mt][nt][1] + b1);
                *(float2*)&S[(size_t)(r0 + 8) * SPAD + col] =
                    make_float2(acc[mt][nt][2] + b0, acc[mt][nt][3] + b1);
            }
        }
        __syncthreads();

        const int r = tid >> 2, qd = tid & 3;        // 128 rows x 4 quarters (32 cols each)
        const size_t grow = (size_t)m0 + r;
        const float* erow = EPS + grow * 128 + qd * 32;
        __nv_bfloat16* ZB = (__nv_bfloat16*)Cv;
        float kla = 0.f;
        uint32_t zbuf[16];
#pragma unroll
        for (int j = 0; j < 16; ++j) {
            int c = qd * 32 + 2 * j;
            float mu0 = S[(size_t)r * SPAD + c];
            float mu1 = S[(size_t)r * SPAD + c + 1];
            float l0  = S[(size_t)r * SPAD + c + 128];
            float l1  = S[(size_t)r * SPAD + c + 129];
            float2 ep = *(const float2*)&erow[2 * j];
            float s0 = expf(l0), s1 = expf(l1);
            float z0 = fmaf(s0, ep.x, mu0), z1 = fmaf(s1, ep.y, mu1);
            __nv_bfloat162 p = __float22bfloat162_rn(make_float2(z0, z1));
            zbuf[j] = *(uint32_t*)&p;
            kla += s0 * s0 + mu0 * mu0 - 2.f * l0 - 1.f;
            kla += s1 * s1 + mu1 * mu1 - 2.f * l1 - 1.f;
        }
        int4* zo = (int4*)(ZB + grow * 128 + qd * 32);
#pragma unroll
        for (int q = 0; q < 4; ++q) zo[q] = ((int4*)zbuf)[q];
        kla += __shfl_xor_sync(0xffffffffu, kla, 1);
        kla += __shfl_xor_sync(0xffffffffu, kla, 2);
        if (qd == 0) LP[grow] = 0.5f * kla;
    }
}

// ---------------- fused prep kernel ------------------------------------------
__device__ __forceinline__ void do_transpose(float (*ts)[33],
                                             const float* __restrict__ in,
                                             __nv_bfloat16* __restrict__ out,
                                             int K, int N, int rowOff, int bx, int by, int tid) {
    int tx = tid & 31, ty = tid >> 5;
    int k0 = by * 32, n0 = bx * 32;
    for (int j = ty; j < 32; j += 8)
        ts[j][tx] = in[(size_t)(k0 + j) * N + n0 + tx];
    __syncthreads();
    for (int j = ty; j < 32; j += 8)
        out[(size_t)(rowOff + n0 + j) * K + k0 + tx] = __float2bfloat16(ts[tx][j]);
}

__global__ __launch_bounds__(256)
void prep_kernel(const float* __restrict__ x,
                 const float* __restrict__ We1, const float* __restrict__ Wmu,
                 const float* __restrict__ Wls, const float* __restrict__ Wd1,
                 const float* __restrict__ Wd2, const float* __restrict__ bmu,
                 const float* __restrict__ bls,
                 __nv_bfloat16* __restrict__ xb, __nv_bfloat16* __restrict__ We1t,
                 __nv_bfloat16* __restrict__ Wmlt, __nv_bfloat16* __restrict__ Wd1t,
                 __nv_bfloat16* __restrict__ Wd2t, float* __restrict__ bml)
{
    __shared__ float ts[32][33];
    const int b = blockIdx.x, tid = threadIdx.x;
    if (b < 16384) {
        size_t i = ((size_t)b * 256 + tid) * 8;
        float4 a = *(const float4*)(x + i);
        float4 c = *(const float4*)(x + i + 4);
        __nv_bfloat162 p[4];
        p[0] = __float22bfloat162_rn(make_float2(a.x, a.y));
        p[1] = __float22bfloat162_rn(make_float2(a.z, a.w));
        p[2] = __float22bfloat162_rn(make_float2(c.x, c.y));
        p[3] = __float22bfloat162_rn(make_float2(c.z, c.w));
        *(int4*)(xb + i) = *(int4*)p;
    } else if (b < 17408) {
        int r = b - 16384;  do_transpose(ts, We1, We1t, 1024, 1024, 0,   r % 32, r / 32, tid);
    } else if (b < 17536) {
        int r = b - 17408;  do_transpose(ts, Wmu, Wmlt, 1024, 128,  0,   r % 4,  r / 4,  tid);
    } else if (b < 17664) {
        int r = b - 17536;  do_transpose(ts, Wls, Wmlt, 1024, 128,  128, r % 4,  r / 4,  tid);
    } else if (b < 17792) {
        int r = b - 17664;  do_transpose(ts, Wd1, Wd1t, 128,  1024, 0,   r % 32, r / 32, tid);
    } else if (b < 18816) {
        int r = b - 17792;  do_transpose(ts, Wd2, Wd2t, 1024, 1024, 0,   r % 32, r / 32, tid);
    } else {
        bml[tid] = (tid < 128) ? bmu[tid] : bls[tid - 128];
    }
}

__global__ void finalize_kernel(const float* __restrict__ kl_, const float* __restrict__ lp_,
                                float* __restrict__ out) {
    int r = blockIdx.x * blockDim.x + threadIdx.x;
    float s = 0.f;
#pragma unroll
    for (int j = 0; j < 32; j++) s += lp_[(size_t)r * 32 + j];
    out[r] = s - kl_[r];
}

// ---------------- launch ------------------------------------------------------
extern "C" void kernel_launch(void* const* d_in, const int* in_sizes, int n_in,
                              void* d_out, int out_size)
{
    const float* x   = (const float*)d_in[0];
    const float* eps = (const float*)d_in[1];
    const float* We1 = (const float*)d_in[2];
    const float* be1 = (const float*)d_in[3];
    const float* Wmu = (const float*)d_in[4];
    const float* bmu = (const float*)d_in[5];
    const float* Wls = (const float*)d_in[6];
    const float* bls = (const float*)d_in[7];
    const float* Wd1 = (const float*)d_in[8];
    const float* bd1 = (const float*)d_in[9];
    const float* Wd2 = (const float*)d_in[10];
    const float* bd2 = (const float*)d_in[11];
    float* out = (float*)d_out;

    __nv_bfloat16 *xb, *hb, *zb, *hdb, *We1t, *Wmlt, *Wd1t, *Wd2t;
    float *kl, *lp, *bml;
    cudaGetSymbolAddress((void**)&xb,   g_xb);
    cudaGetSymbolAddress((void**)&hb,   g_hb);
    cudaGetSymbolAddress((void**)&zb,   g_zb);
    cudaGetSymbolAddress((void**)&hdb,  g_hdb);
    cudaGetSymbolAddress((void**)&kl,   g_kl);
    cudaGetSymbolAddress((void**)&lp,   g_lp);
    cudaGetSymbolAddress((void**)&We1t, g_We1t);
    cudaGetSymbolAddress((void**)&Wmlt, g_Wmlt);
    cudaGetSymbolAddress((void**)&Wd1t, g_Wd1t);
    cudaGetSymbolAddress((void**)&Wd2t, g_Wd2t);
    cudaGetSymbolAddress((void**)&bml,  g_bml);

    cudaFuncSetAttribute((const void*)mma_gemm<0,256,128>, cudaFuncAttributeMaxDynamicSharedMemorySize, SMEM_SZ);
    cudaFuncSetAttribute((const void*)mma_gemm<2,256,128>, cudaFuncAttributeMaxDynamicSharedMemorySize, SMEM_SZ);
    cudaFuncSetAttribute((const void*)mma_gemm<3,128,256>, cudaFuncAttributeMaxDynamicSharedMemorySize, SMEM_SZ);

    // 0) fused prep
    prep_kernel<<<18817, 256>>>(x, We1, Wmu, Wls, Wd1, Wd2, bmu, bls,
                                xb, We1t, Wmlt, Wd1t, Wd2t, bml);
    // 1) h = relu(x @ We1 + be1) -> bf16
    mma_gemm<0,256,128><<<dim3(8, 128), NTHR, SMEM_SZ>>>(xb, D_IN, We1t, be1, hb, D_H,
                                                         nullptr, nullptr, nullptr, D_IN);
    // 2) [mu|ls] GEMM + fused reparam/KL -> zb (bf16), kl
    mma_gemm<3,128,256><<<dim3(1, 256), NTHR, SMEM_SZ>>>(hb, D_H, Wmlt, bml, zb, D_L,
                                                         nullptr, kl, eps, D_H);
    // 3) hd = relu(z @ Wd1 + bd1) -> bf16
    mma_gemm<0,256,128><<<dim3(8, 128), NTHR, SMEM_SZ>>>(zb, D_L, Wd1t, bd1, hdb, D_H,
                                                         nullptr, nullptr, nullptr, D_L);
    // 4) Bernoulli log-lik partials from hd @ Wd2 + bd2
    mma_gemm<2,256,128><<<dim3(8, 128), NTHR, SMEM_SZ>>>(hdb, D_H, Wd2t, bd2, nullptr, 0,
                                                         xb, lp, nullptr, D_H);
    // 5) out = log_px - kl
    finalize_kernel<<<BATCH / 256, 256>>>(kl, lp, out);
}

// round 7
// speedup vs baseline: 6.7159x; 1.0072x over previous
#include <cuda_runtime.h>
#include <cuda_bf16.h>
#include <cstdint>
#include <math.h>

#define BATCH 32768
#define D_IN  1024
#define D_H   1024
#define D_L   128

// ---------------- scratch (__device__ globals; alloc-free rule) -------------
__device__ __align__(16) __nv_bfloat16 g_xb [BATCH * D_IN];
__device__ __align__(16) __nv_bfloat16 g_hb [BATCH * D_H];
__device__ __align__(16) __nv_bfloat16 g_zb [BATCH * D_L];
__device__ __align__(16) __nv_bfloat16 g_hdb[BATCH * D_H];
__device__ __align__(16) float         g_kl [BATCH];
__device__ __align__(16) float         g_lp [BATCH * 32];
__device__ __align__(16) __nv_bfloat16 g_We1t[D_H * D_IN];     // [N][K] K-major
__device__ __align__(16) __nv_bfloat16 g_Wmlt[256 * D_H];
__device__ __align__(16) __nv_bfloat16 g_Wd1t[D_H * D_L];
__device__ __align__(16) __nv_bfloat16 g_Wd2t[D_IN * D_H];
__device__ __align__(16) float         g_bml [256];

// ---------------- helpers ----------------------------------------------------
__device__ __forceinline__ uint32_t smem_u32(const void* p) {
    uint32_t a;
    asm("{ .reg .u64 t; cvta.to.shared.u64 t, %1; cvt.u32.u64 %0, t; }" : "=r"(a) : "l"(p));
    return a;
}

#define CP_ASYNC16(dst, src) \
    asm volatile("cp.async.cg.shared.global [%0], [%1], 16;" :: "r"(dst), "l"(src))
#define CP_COMMIT() asm volatile("cp.async.commit_group;" ::: "memory")
#define CP_WAIT0()  asm volatile("cp.async.wait_group 0;" ::: "memory")
#define CP_WAIT1()  asm volatile("cp.async.wait_group 1;" ::: "memory")

__device__ __forceinline__ void ldsm4(uint32_t& r0, uint32_t& r1, uint32_t& r2, uint32_t& r3,
                                      uint32_t addr) {
    asm volatile("ldmatrix.sync.aligned.m8n8.x4.shared.b16 {%0,%1,%2,%3}, [%4];"
                 : "=r"(r0), "=r"(r1), "=r"(r2), "=r"(r3) : "r"(addr));
}

__device__ __forceinline__ void mma16816(float* c, const uint32_t* a, const uint32_t* b) {
    asm volatile("mma.sync.aligned.m16n8k16.row.col.f32.bf16.bf16.f32 "
                 "{%0,%1,%2,%3}, {%4,%5,%6,%7}, {%8,%9}, {%0,%1,%2,%3};"
                 : "+f"(c[0]), "+f"(c[1]), "+f"(c[2]), "+f"(c[3])
                 : "r"(a[0]), "r"(a[1]), "r"(a[2]), "r"(a[3]), "r"(b[0]), "r"(b[1]));
}

// ---------------- HMMA GEMM: C[M,N] = A[M,K] @ Bt[N,K]^T (+epilogue) ---------
// 256 threads = 8 warps. BM=128 (WM=2 warp rows), warp tile 64 x (BN/4).
// 3-stage cp.async pipeline, ONE __syncthreads per K-chunk of 64.
// MINB=2 -> two CTAs per SM (96KB smem, <=128 regs each) for latency overlap.
// EPI 0: bf16 relu(acc+bias)
// EPI 2: Bernoulli partial -> LP[row*32 + bn*4 + wn]
// EPI 3: fused reparam (BM=128,BN=256, MINB=1): Cv=zb bf16, LP=kl, EPS=eps
static constexpr int NSTAGE = 3;
static constexpr int NTHR = 256;

template<int BM, int BN> struct GemmCfg {
    static constexpr int STAGE = (BM + BN) * 64 * 2;
    static constexpr int SMEM  = NSTAGE * STAGE + 128;
};

template<int EPI, int BM, int BN, int MINB>
__global__ __launch_bounds__(NTHR, MINB)
void mma_gemm(const __nv_bfloat16* __restrict__ A, int lda,
              const __nv_bfloat16* __restrict__ Bt,
              const float* __restrict__ bias,
              void* __restrict__ Cv, int ldc,
              const __nv_bfloat16* __restrict__ XB,
              float* __restrict__ LP,
              const float* __restrict__ EPS, int K)
{
    extern __shared__ char smraw[];
    uint32_t raw = smem_u32(smraw);
    uint32_t sbase = (raw + 127u) & ~127u;

    constexpr int WM  = BM / 64;               // warp rows (2)
    constexpr int WNG = 8 / WM;                // warp cols (4)
    constexpr int WTN = BN / WNG;              // warp N tile (32 or 64)
    constexpr int NT  = WTN / 8;               // mma n-tiles per warp (4 or 8)
    constexpr int BLD = WTN / 16;              // B ldsm4 per kk (2 or 4)
    constexpr int A_BYTES = BM * 64 * 2;
    constexpr int STAGE_BYTES = GemmCfg<BM, BN>::STAGE;
    constexpr int AI = BM / 32, BI = BN / 32;  // loader iters (256 thr, 16B each)

    const int tid  = threadIdx.x, lane = tid & 31, wid = tid >> 5;
    const int wm   = wid % WM, wn = wid / WM;
    const int bn   = blockIdx.x;
    const int m0   = blockIdx.y * BM, col0 = bn * BN;

    const __nv_bfloat16* Ag = A  + (size_t)m0   * lda;
    const __nv_bfloat16* Bg = Bt + (size_t)col0 * K;

    const int T = K >> 6;
    const int P = (T < NSTAGE - 1) ? T : (NSTAGE - 1);

    float acc[4][NT][4];
#pragma unroll
    for (int mt = 0; mt < 4; ++mt)
#pragma unroll
        for (int nt = 0; nt < NT; ++nt)
#pragma unroll
            for (int q = 0; q < 4; ++q) acc[mt][nt][q] = 0.f;

    auto issue_stage = [&](int kt) {
        uint32_t sA = sbase + (uint32_t)(kt % NSTAGE) * STAGE_BYTES;
        uint32_t sB = sA + A_BYTES;
        const __nv_bfloat16* Ak = Ag + kt * 64;
        const __nv_bfloat16* Bk = Bg + kt * 64;
#pragma unroll
        for (int i = 0; i < AI; ++i) {
            int idx = tid + i * NTHR;
            int rr = idx >> 3, cc = idx & 7;
            uint32_t sw = (uint32_t)(rr * 128 + ((cc ^ (rr & 7)) << 4));
            CP_ASYNC16(sA + sw, Ak + (size_t)rr * lda + cc * 8);
        }
#pragma unroll
        for (int i = 0; i < BI; ++i) {
            int idx = tid + i * NTHR;
            int rr = idx >> 3, cc = idx & 7;
            uint32_t sw = (uint32_t)(rr * 128 + ((cc ^ (rr & 7)) << 4));
            CP_ASYNC16(sB + sw, Bk + (size_t)rr * K + cc * 8);
        }
        CP_COMMIT();
    };

    for (int kt = 0; kt < P; ++kt) issue_stage(kt);
    int committed = P;

    const int g = lane >> 3, lq = lane & 7;

    for (int t = 0; t < T; ++t) {
        int allow = committed - t - 1;
        if (allow >= 1) { CP_WAIT1(); } else { CP_WAIT0(); }
        __syncthreads();

        if (t + NSTAGE - 1 < T) { issue_stage(t + NSTAGE - 1); committed++; }

        uint32_t sA = sbase + (uint32_t)(t % NSTAGE) * STAGE_BYTES;
        uint32_t sB = sA + A_BYTES;

#pragma unroll
        for (int kk = 0; kk < 4; ++kk) {
            uint32_t a[4][4];
#pragma unroll
            for (int mt = 0; mt < 4; ++mt) {
                int row = wm * 64 + mt * 16 + (g & 1) * 8 + lq;
                int kc  = kk * 2 + (g >> 1);
                uint32_t ad = sA + (uint32_t)(row * 128 + ((kc ^ (row & 7)) << 4));
                ldsm4(a[mt][0], a[mt][1], a[mt][2], a[mt][3], ad);
            }
            uint32_t b[NT][2];
#pragma unroll
            for (int p = 0; p < BLD; ++p) {
                int row = wn * WTN + (p * 2 + (g >> 1)) * 8 + lq;
                int kc  = kk * 2 + (g & 1);
                uint32_t ad = sB + (uint32_t)(row * 128 + ((kc ^ (row & 7)) << 4));
                uint32_t r0, r1, r2, r3;
                ldsm4(r0, r1, r2, r3, ad);
                b[p * 2][0] = r0; b[p * 2][1] = r1;
                b[p * 2 + 1][0] = r2; b[p * 2 + 1][1] = r3;
            }
#pragma unroll
            for (int mt = 0; mt < 4; ++mt)
#pragma unroll
                for (int nt = 0; nt < NT; ++nt)
                    mma16816(acc[mt][nt], a[mt], b[nt]);
        }
    }

    // ---------------- epilogue ----------------
    const int rbase = m0 + wm * 64 + (lane >> 2);
    const int cq    = (lane & 3) * 2;

    if (EPI == 0) {
        __nv_bfloat16* C = (__nv_bfloat16*)Cv;
#pragma unroll
        for (int mt = 0; mt < 4; ++mt) {
            int r0 = rbase + mt * 16;
#pragma unroll
            for (int nt = 0; nt < NT; ++nt) {
                int col = col0 + wn * WTN + nt * 8 + cq;
                float b0 = __ldg(bias + col), b1 = __ldg(bias + col + 1);
                float v0 = fmaxf(acc[mt][nt][0] + b0, 0.f);
                float v1 = fmaxf(acc[mt][nt][1] + b1, 0.f);
                float v2 = fmaxf(acc[mt][nt][2] + b0, 0.f);
                float v3 = fmaxf(acc[mt][nt][3] + b1, 0.f);
                __nv_bfloat162 p0 = __float22bfloat162_rn(make_float2(v0, v1));
                __nv_bfloat162 p1 = __float22bfloat162_rn(make_float2(v2, v3));
                *(uint32_t*)(C + (size_t)r0 * ldc + col)       = *(uint32_t*)&p0;
                *(uint32_t*)(C + (size_t)(r0 + 8) * ldc + col) = *(uint32_t*)&p1;
            }
        }
    } else if (EPI == 2) {
#pragma unroll
        for (int mt = 0; mt < 4; ++mt) {
            int r0 = rbase + mt * 16;
            float s0 = 0.f, s1 = 0.f;
#pragma unroll
            for (int nt = 0; nt < NT; ++nt) {
                int col = col0 + wn * WTN + nt * 8 + cq;
                float b0 = __ldg(bias + col), b1 = __ldg(bias + col + 1);
                uint32_t xw0 = *(const uint32_t*)(XB + (size_t)r0 * D_IN + col);
                uint32_t xw1 = *(const uint32_t*)(XB + (size_t)(r0 + 8) * D_IN + col);
                __nv_bfloat162 xp0 = *(__nv_bfloat162*)&xw0;
                __nv_bfloat162 xp1 = *(__nv_bfloat162*)&xw1;
                float a0 = acc[mt][nt][0] + b0, a1 = acc[mt][nt][1] + b1;
                float a2 = acc[mt][nt][2] + b0, a3 = acc[mt][nt][3] + b1;
                float t0 = (__bfloat162float(xp0.x) > 0.5f) ? -a0 : a0;
                float t1 = (__bfloat162float(xp0.y) > 0.5f) ? -a1 : a1;
                float t2 = (__bfloat162float(xp1.x) > 0.5f) ? -a2 : a2;
                float t3 = (__bfloat162float(xp1.y) > 0.5f) ? -a3 : a3;
                s0 += fmaxf(t0, 0.f) + log1pf(__expf(-fabsf(t0)));
                s0 += fmaxf(t1, 0.f) + log1pf(__expf(-fabsf(t1)));
                s1 += fmaxf(t2, 0.f) + log1pf(__expf(-fabsf(t2)));
                s1 += fmaxf(t3, 0.f) + log1pf(__expf(-fabsf(t3)));
            }
            s0 += __shfl_xor_sync(0xffffffffu, s0, 1);
            s0 += __shfl_xor_sync(0xffffffffu, s0, 2);
            s1 += __shfl_xor_sync(0xffffffffu, s1, 1);
            s1 += __shfl_xor_sync(0xffffffffu, s1, 2);
            if ((lane & 3) == 0) {
                LP[(size_t)r0 * 32 + bn * 4 + wn]       = -s0;
                LP[(size_t)(r0 + 8) * 32 + bn * 4 + wn] = -s1;
            }
        }
    } else {
        // EPI 3: fused reparam + KL. BM=128, BN=256 (cols 0..127 = mu, 128..255 = ls).
        constexpr int SPAD = 258;
        float* S = (float*)(smraw + (sbase - raw));
        __syncthreads();
        const int rl = wm * 64 + (lane >> 2);
#pragma unroll
        for (int mt = 0; mt < 4; ++mt) {
            int r0 = rl + mt * 16;
#pragma unroll
            for (int nt = 0; nt < NT; ++nt) {
                int col = wn * WTN + nt * 8 + cq;
                float b0 = __ldg(bias + col), b1 = __ldg(bias + col + 1);
                *(float2*)&S[(size_t)r0 * SPAD + col] =
                    make_float2(acc[mt][nt][0] + b0, acc[mt][nt][1] + b1);
                *(float2*)&S[(size_t)(r0 + 8) * SPAD + col] =
                    make_float2(acc[mt][nt][2] + b0, acc[mt][nt][3] + b1);
            }
        }
        __syncthreads();

        const int r = tid >> 1, h = tid & 1;         // 128 rows x 2 halves (64 cols each)
        const size_t grow = (size_t)m0 + r;
        const float* erow = EPS + grow * 128 + h * 64;
        __nv_bfloat16* ZB = (__nv_bfloat16*)Cv;
        float kla = 0.f;
        uint32_t zbuf[32];
#pragma unroll
        for (int j = 0; j < 32; ++j) {
            int c = h * 64 + 2 * j;
            float mu0 = S[(size_t)r * SPAD + c];
            float mu1 = S[(size_t)r * SPAD + c + 1];
            float l0  = S[(size_t)r * SPAD + c + 128];
            float l1  = S[(size_t)r * SPAD + c + 129];
            float2 ep = *(const float2*)&erow[2 * j];
            float s0 = expf(l0), s1 = expf(l1);
            float z0 = fmaf(s0, ep.x, mu0), z1 = fmaf(s1, ep.y, mu1);
            __nv_bfloat162 p = __float22bfloat162_rn(make_float2(z0, z1));
            zbuf[j] = *(uint32_t*)&p;
            kla += s0 * s0 + mu0 * mu0 - 2.f * l0 - 1.f;
            kla += s1 * s1 + mu1 * mu1 - 2.f * l1 - 1.f;
        }
        int4* zo = (int4*)(ZB + grow * 128 + h * 64);
#pragma unroll
        for (int q = 0; q < 8; ++q) zo[q] = ((int4*)zbuf)[q];
        kla += __shfl_xor_sync(0xffffffffu, kla, 1);
        if (h == 0) LP[grow] = 0.5f * kla;
    }
}

// ---------------- fused prep kernel ------------------------------------------
__device__ __forceinline__ void do_transpose(float (*ts)[33],
                                             const float* __restrict__ in,
                                             __nv_bfloat16* __restrict__ out,
                                             int K, int N, int rowOff, int bx, int by, int tid) {
    int tx = tid & 31, ty = tid >> 5;
    int k0 = by * 32, n0 = bx * 32;
    for (int j = ty; j < 32; j += 8)
        ts[j][tx] = in[(size_t)(k0 + j) * N + n0 + tx];
    __syncthreads();
    for (int j = ty; j < 32; j += 8)
        out[(size_t)(rowOff + n0 + j) * K + k0 + tx] = __float2bfloat16(ts[tx][j]);
}

__global__ __launch_bounds__(256)
void prep_kernel(const float* __restrict__ x,
                 const float* __restrict__ We1, const float* __restrict__ Wmu,
                 const float* __restrict__ Wls, const float* __restrict__ Wd1,
                 const float* __restrict__ Wd2, const float* __restrict__ bmu,
                 const float* __restrict__ bls,
                 __nv_bfloat16* __restrict__ xb, __nv_bfloat16* __restrict__ We1t,
                 __nv_bfloat16* __restrict__ Wmlt, __nv_bfloat16* __restrict__ Wd1t,
                 __nv_bfloat16* __restrict__ Wd2t, float* __restrict__ bml)
{
    __shared__ float ts[32][33];
    const int b = blockIdx.x, tid = threadIdx.x;
    if (b < 16384) {
        size_t i = ((size_t)b * 256 + tid) * 8;
        float4 a = *(const float4*)(x + i);
        float4 c = *(const float4*)(x + i + 4);
        __nv_bfloat162 p[4];
        p[0] = __float22bfloat162_rn(make_float2(a.x, a.y));
        p[1] = __float22bfloat162_rn(make_float2(a.z, a.w));
        p[2] = __float22bfloat162_rn(make_float2(c.x, c.y));
        p[3] = __float22bfloat162_rn(make_float2(c.z, c.w));
        *(int4*)(xb + i) = *(int4*)p;
    } else if (b < 17408) {
        int r = b - 16384;  do_transpose(ts, We1, We1t, 1024, 1024, 0,   r % 32, r / 32, tid);
    } else if (b < 17536) {
        int r = b - 17408;  do_transpose(ts, Wmu, Wmlt, 1024, 128,  0,   r % 4,  r / 4,  tid);
    } else if (b < 17664) {
        int r = b - 17536;  do_transpose(ts, Wls, Wmlt, 1024, 128,  128, r % 4,  r / 4,  tid);
    } else if (b < 17792) {
        int r = b - 17664;  do_transpose(ts, Wd1, Wd1t, 128,  1024, 0,   r % 32, r / 32, tid);
    } else if (b < 18816) {
        int r = b - 17792;  do_transpose(ts, Wd2, Wd2t, 1024, 1024, 0,   r % 32, r / 32, tid);
    } else {
        bml[tid] = (tid < 128) ? bmu[tid] : bls[tid - 128];
    }
}

__global__ void finalize_kernel(const float* __restrict__ kl_, const float* __restrict__ lp_,
                                float* __restrict__ out) {
    int r = blockIdx.x * blockDim.x + threadIdx.x;
    float s = 0.f;
#pragma unroll
    for (int j = 0; j < 32; j++) s += lp_[(size_t)r * 32 + j];
    out[r] = s - kl_[r];
}

// ---------------- launch ------------------------------------------------------
extern "C" void kernel_launch(void* const* d_in, const int* in_sizes, int n_in,
                              void* d_out, int out_size)
{
    const float* x   = (const float*)d_in[0];
    const float* eps = (const float*)d_in[1];
    const float* We1 = (const float*)d_in[2];
    const float* be1 = (const float*)d_in[3];
    const float* Wmu = (const float*)d_in[4];
    const float* bmu = (const float*)d_in[5];
    const float* Wls = (const float*)d_in[6];
    const float* bls = (const float*)d_in[7];
    const float* Wd1 = (const float*)d_in[8];
    const float* bd1 = (const float*)d_in[9];
    const float* Wd2 = (const float*)d_in[10];
    const float* bd2 = (const float*)d_in[11];
    float* out = (float*)d_out;

    __nv_bfloat16 *xb, *hb, *zb, *hdb, *We1t, *Wmlt, *Wd1t, *Wd2t;
    float *kl, *lp, *bml;
    cudaGetSymbolAddress((void**)&xb,   g_xb);
    cudaGetSymbolAddress((void**)&hb,   g_hb);
    cudaGetSymbolAddress((void**)&zb,   g_zb);
    cudaGetSymbolAddress((void**)&hdb,  g_hdb);
    cudaGetSymbolAddress((void**)&kl,   g_kl);
    cudaGetSymbolAddress((void**)&lp,   g_lp);
    cudaGetSymbolAddress((void**)&We1t, g_We1t);
    cudaGetSymbolAddress((void**)&Wmlt, g_Wmlt);
    cudaGetSymbolAddress((void**)&Wd1t, g_Wd1t);
    cudaGetSymbolAddress((void**)&Wd2t, g_Wd2t);
    cudaGetSymbolAddress((void**)&bml,  g_bml);

    constexpr int SM_SMALL = GemmCfg<128,128>::SMEM;   // 3 x 32KB + pad
    constexpr int SM_BIG   = GemmCfg<128,256>::SMEM;   // 3 x 48KB + pad

    cudaFuncSetAttribute((const void*)mma_gemm<0,128,128,2>, cudaFuncAttributeMaxDynamicSharedMemorySize, SM_SMALL);
    cudaFuncSetAttribute((const void*)mma_gemm<2,128,128,2>, cudaFuncAttributeMaxDynamicSharedMemorySize, SM_SMALL);
    cudaFuncSetAttribute((const void*)mma_gemm<3,128,256,1>, cudaFuncAttributeMaxDynamicSharedMemorySize, SM_BIG);

    // 0) fused prep
    prep_kernel<<<18817, 256>>>(x, We1, Wmu, Wls, Wd1, Wd2, bmu, bls,
                                xb, We1t, Wmlt, Wd1t, Wd2t, bml);
    // 1) h = relu(x @ We1 + be1) -> bf16
    mma_gemm<0,128,128,2><<<dim3(8, 256), NTHR, SM_SMALL>>>(xb, D_IN, We1t, be1, hb, D_H,
                                                            nullptr, nullptr, nullptr, D_IN);
    // 2) [mu|ls] GEMM + fused reparam/KL -> zb (bf16), kl
    mma_gemm<3,128,256,1><<<dim3(1, 256), NTHR, SM_BIG>>>(hb, D_H, Wmlt, bml, zb, D_L,
                                                          nullptr, kl, eps, D_H);
    // 3) hd = relu(z @ Wd1 + bd1) -> bf16
    mma_gemm<0,128,128,2><<<dim3(8, 256), NTHR, SM_SMALL>>>(zb, D_L, Wd1t, bd1, hdb, D_H,
                                                            nullptr, nullptr, nullptr, D_L);
    // 4) Bernoulli log-lik partials from hd @ Wd2 + bd2
    mma_gemm<2,128,128,2><<<dim3(8, 256), NTHR, SM_SMALL>>>(hdb, D_H, Wd2t, bd2, nullptr, 0,
                                                            xb, lp, nullptr, D_H);
    // 5) out = log_px - kl
    finalize_kernel<<<BATCH / 256, 256>>>(kl, lp, out);
}

// round 8
// speedup vs baseline: 6.7421x; 1.0039x over previous
#include <cuda_runtime.h>
#include <cuda_bf16.h>
#include <cstdint>
#include <math.h>

#define BATCH 32768
#define D_IN  1024
#define D_H   1024
#define D_L   128

// ---------------- scratch (__device__ globals; alloc-free rule) -------------
__device__ __align__(16) __nv_bfloat16 g_xb [BATCH * D_IN];
__device__ __align__(16) __nv_bfloat16 g_hb [BATCH * D_H];
__device__ __align__(16) __nv_bfloat16 g_hdb[BATCH * D_H];
__device__ __align__(16) float         g_kl [BATCH];
__device__ __align__(16) float         g_lp [BATCH * 32];
__device__ __align__(16) __nv_bfloat16 g_We1t[D_H * D_IN];     // [N][K] K-major
__device__ __align__(16) __nv_bfloat16 g_Wmlt[256 * D_H];
__device__ __align__(16) __nv_bfloat16 g_Wd1t[D_H * D_L];
__device__ __align__(16) __nv_bfloat16 g_Wd2t[D_IN * D_H];
__device__ __align__(16) float         g_bml [256];

// ---------------- helpers ----------------------------------------------------
__device__ __forceinline__ uint32_t smem_u32(const void* p) {
    uint32_t a;
    asm("{ .reg .u64 t; cvta.to.shared.u64 t, %1; cvt.u32.u64 %0, t; }" : "=r"(a) : "l"(p));
    return a;
}

#define CP_ASYNC16(dst, src) \
    asm volatile("cp.async.cg.shared.global [%0], [%1], 16;" :: "r"(dst), "l"(src))
#define CP_COMMIT() asm volatile("cp.async.commit_group;" ::: "memory")
#define CP_WAIT0()  asm volatile("cp.async.wait_group 0;" ::: "memory")
#define CP_WAIT1()  asm volatile("cp.async.wait_group 1;" ::: "memory")

__device__ __forceinline__ void ldsm4(uint32_t& r0, uint32_t& r1, uint32_t& r2, uint32_t& r3,
                                      uint32_t addr) {
    asm volatile("ldmatrix.sync.aligned.m8n8.x4.shared.b16 {%0,%1,%2,%3}, [%4];"
                 : "=r"(r0), "=r"(r1), "=r"(r2), "=r"(r3) : "r"(addr));
}

__device__ __forceinline__ void mma16816(float* c, const uint32_t* a, const uint32_t* b) {
    asm volatile("mma.sync.aligned.m16n8k16.row.col.f32.bf16.bf16.f32 "
                 "{%0,%1,%2,%3}, {%4,%5,%6,%7}, {%8,%9}, {%0,%1,%2,%3};"
                 : "+f"(c[0]), "+f"(c[1]), "+f"(c[2]), "+f"(c[3])
                 : "r"(a[0]), "r"(a[1]), "r"(a[2]), "r"(a[3]), "r"(b[0]), "r"(b[1]));
}

// ---------------- HMMA GEMM: C[M,N] = A[M,K] @ Bt[N,K]^T (+epilogue) ---------
// 256 threads = 8 warps. BM=128 (WM=2 warp rows), warp tile 64 x (BN/4).
// 3-stage cp.async pipeline, ONE __syncthreads per K-chunk of 64.
// EPI 0: bf16 relu(acc+bias)                      (MINB=2: two CTAs/SM)
// EPI 2: Bernoulli partial -> LP[row*32 + bn*4 + wn]
// EPI 3: fused reparam + KL + hd = relu(z @ W2^T + B2) -> C2 (MINB=1)
static constexpr int NSTAGE = 3;
static constexpr int NTHR = 256;

template<int BM, int BN> struct GemmCfg {
    static constexpr int STAGE = (BM + BN) * 64 * 2;
    static constexpr int SMEM  = NSTAGE * STAGE + 128;
};

template<int EPI, int BM, int BN, int MINB>
__global__ __launch_bounds__(NTHR, MINB)
void mma_gemm(const __nv_bfloat16* __restrict__ A, int lda,
              const __nv_bfloat16* __restrict__ Bt,
              const float* __restrict__ bias,
              void* __restrict__ Cv, int ldc,
              const __nv_bfloat16* __restrict__ XB,
              float* __restrict__ LP,
              const float* __restrict__ EPS,
              const __nv_bfloat16* __restrict__ W2,
              const float* __restrict__ B2,
              __nv_bfloat16* __restrict__ C2, int K)
{
    extern __shared__ char smraw[];
    uint32_t raw = smem_u32(smraw);
    uint32_t sbase = (raw + 127u) & ~127u;
    char* sm = smraw + (sbase - raw);

    constexpr int WM  = BM / 64;               // warp rows (2)
    constexpr int WNG = 8 / WM;                // warp cols (4)
    constexpr int WTN = BN / WNG;              // warp N tile (32 or 64)
    constexpr int NT  = WTN / 8;               // mma n-tiles per warp
    constexpr int BLD = WTN / 16;              // B ldsm4 per kk
    constexpr int A_BYTES = BM * 64 * 2;
    constexpr int STAGE_BYTES = GemmCfg<BM, BN>::STAGE;
    constexpr int AI = BM / 32, BI = BN / 32;

    const int tid  = threadIdx.x, lane = tid & 31, wid = tid >> 5;
    const int wm   = wid % WM, wn = wid / WM;
    const int bn   = blockIdx.x;
    const int m0   = blockIdx.y * BM, col0 = bn * BN;

    const __nv_bfloat16* Ag = A  + (size_t)m0   * lda;
    const __nv_bfloat16* Bg = Bt + (size_t)col0 * K;

    const int T = K >> 6;
    const int P = (T < NSTAGE - 1) ? T : (NSTAGE - 1);

    float acc[4][NT][4];
#pragma unroll
    for (int mt = 0; mt < 4; ++mt)
#pragma unroll
        for (int nt = 0; nt < NT; ++nt)
#pragma unroll
            for (int q = 0; q < 4; ++q) acc[mt][nt][q] = 0.f;

    auto issue_stage = [&](int kt) {
        uint32_t sA = sbase + (uint32_t)(kt % NSTAGE) * STAGE_BYTES;
        uint32_t sB = sA + A_BYTES;
        const __nv_bfloat16* Ak = Ag + kt * 64;
        const __nv_bfloat16* Bk = Bg + kt * 64;
#pragma unroll
        for (int i = 0; i < AI; ++i) {
            int idx = tid + i * NTHR;
            int rr = idx >> 3, cc = idx & 7;
            uint32_t sw = (uint32_t)(rr * 128 + ((cc ^ (rr & 7)) << 4));
            CP_ASYNC16(sA + sw, Ak + (size_t)rr * lda + cc * 8);
        }
#pragma unroll
        for (int i = 0; i < BI; ++i) {
            int idx = tid + i * NTHR;
            int rr = idx >> 3, cc = idx & 7;
            uint32_t sw = (uint32_t)(rr * 128 + ((cc ^ (rr & 7)) << 4));
            CP_ASYNC16(sB + sw, Bk + (size_t)rr * K + cc * 8);
        }
        CP_COMMIT();
    };

    for (int kt = 0; kt < P; ++kt) issue_stage(kt);
    int committed = P;

    const int g = lane >> 3, lq = lane & 7;

    for (int t = 0; t < T; ++t) {
        int allow = committed - t - 1;
        if (allow >= 1) { CP_WAIT1(); } else { CP_WAIT0(); }
        __syncthreads();

        if (t + NSTAGE - 1 < T) { issue_stage(t + NSTAGE - 1); committed++; }

        uint32_t sA = sbase + (uint32_t)(t % NSTAGE) * STAGE_BYTES;
        uint32_t sB = sA + A_BYTES;

#pragma unroll
        for (int kk = 0; kk < 4; ++kk) {
            uint32_t a[4][4];
#pragma unroll
            for (int mt = 0; mt < 4; ++mt) {
                int row = wm * 64 + mt * 16 + (g & 1) * 8 + lq;
                int kc  = kk * 2 + (g >> 1);
                uint32_t ad = sA + (uint32_t)(row * 128 + ((kc ^ (row & 7)) << 4));
                ldsm4(a[mt][0], a[mt][1], a[mt][2], a[mt][3], ad);
            }
            uint32_t b[NT][2];
#pragma unroll
            for (int p = 0; p < BLD; ++p) {
                int row = wn * WTN + (p * 2 + (g >> 1)) * 8 + lq;
                int kc  = kk * 2 + (g & 1);
                uint32_t ad = sB + (uint32_t)(row * 128 + ((kc ^ (row & 7)) << 4));
                uint32_t r0, r1, r2, r3;
                ldsm4(r0, r1, r2, r3, ad);
                b[p * 2][0] = r0; b[p * 2][1] = r1;
                b[p * 2 + 1][0] = r2; b[p * 2 + 1][1] = r3;
            }
#pragma unroll
            for (int mt = 0; mt < 4; ++mt)
#pragma unroll
                for (int nt = 0; nt < NT; ++nt)
                    mma16816(acc[mt][nt], a[mt], b[nt]);
        }
    }

    // ---------------- epilogue ----------------
    const int rbase = m0 + wm * 64 + (lane >> 2);
    const int cq    = (lane & 3) * 2;

    if (EPI == 0) {
        __nv_bfloat16* C = (__nv_bfloat16*)Cv;
#pragma unroll
        for (int mt = 0; mt < 4; ++mt) {
            int r0 = rbase + mt * 16;
#pragma unroll
            for (int nt = 0; nt < NT; ++nt) {
                int col = col0 + wn * WTN + nt * 8 + cq;
                float b0 = __ldg(bias + col), b1 = __ldg(bias + col + 1);
                float v0 = fmaxf(acc[mt][nt][0] + b0, 0.f);
                float v1 = fmaxf(acc[mt][nt][1] + b1, 0.f);
                float v2 = fmaxf(acc[mt][nt][2] + b0, 0.f);
                float v3 = fmaxf(acc[mt][nt][3] + b1, 0.f);
                __nv_bfloat162 p0 = __float22bfloat162_rn(make_float2(v0, v1));
                __nv_bfloat162 p1 = __float22bfloat162_rn(make_float2(v2, v3));
                *(uint32_t*)(C + (size_t)r0 * ldc + col)       = *(uint32_t*)&p0;
                *(uint32_t*)(C + (size_t)(r0 + 8) * ldc + col) = *(uint32_t*)&p1;
            }
        }
    } else if (EPI == 2) {
#pragma unroll
        for (int mt = 0; mt < 4; ++mt) {
            int r0 = rbase + mt * 16;
            float s0 = 0.f, s1 = 0.f;
#pragma unroll
            for (int nt = 0; nt < NT; ++nt) {
                int col = col0 + wn * WTN + nt * 8 + cq;
                float b0 = __ldg(bias + col), b1 = __ldg(bias + col + 1);
                uint32_t xw0 = *(const uint32_t*)(XB + (size_t)r0 * D_IN + col);
                uint32_t xw1 = *(const uint32_t*)(XB + (size_t)(r0 + 8) * D_IN + col);
                __nv_bfloat162 xp0 = *(__nv_bfloat162*)&xw0;
                __nv_bfloat162 xp1 = *(__nv_bfloat162*)&xw1;
                float a0 = acc[mt][nt][0] + b0, a1 = acc[mt][nt][1] + b1;
                float a2 = acc[mt][nt][2] + b0, a3 = acc[mt][nt][3] + b1;
                float t0 = (__bfloat162float(xp0.x) > 0.5f) ? -a0 : a0;
                float t1 = (__bfloat162float(xp0.y) > 0.5f) ? -a1 : a1;
                float t2 = (__bfloat162float(xp1.x) > 0.5f) ? -a2 : a2;
                float t3 = (__bfloat162float(xp1.y) > 0.5f) ? -a3 : a3;
                s0 += fmaxf(t0, 0.f) + log1pf(__expf(-fabsf(t0)));
                s0 += fmaxf(t1, 0.f) + log1pf(__expf(-fabsf(t1)));
                s1 += fmaxf(t2, 0.f) + log1pf(__expf(-fabsf(t2)));
                s1 += fmaxf(t3, 0.f) + log1pf(__expf(-fabsf(t3)));
            }
            s0 += __shfl_xor_sync(0xffffffffu, s0, 1);
            s0 += __shfl_xor_sync(0xffffffffu, s0, 2);
            s1 += __shfl_xor_sync(0xffffffffu, s1, 1);
            s1 += __shfl_xor_sync(0xffffffffu, s1, 2);
            if ((lane & 3) == 0) {
                LP[(size_t)r0 * 32 + bn * 4 + wn]       = -s0;
                LP[(size_t)(r0 + 8) * 32 + bn * 4 + wn] = -s1;
            }
        }
    } else {
        // EPI 3: fused reparam + KL + hd GEMM. BM=128, BN=256 (mu|ls).
        constexpr int SPAD = 258;
        float* S = (float*)sm;
        __syncthreads();
        const int rl = wm * 64 + (lane >> 2);
#pragma unroll
        for (int mt = 0; mt < 4; ++mt) {
            int r0 = rl + mt * 16;
#pragma unroll
            for (int nt = 0; nt < NT; ++nt) {
                int col = wn * WTN + nt * 8 + cq;
                float b0 = __ldg(bias + col), b1 = __ldg(bias + col + 1);
                *(float2*)&S[(size_t)r0 * SPAD + col] =
                    make_float2(acc[mt][nt][0] + b0, acc[mt][nt][1] + b1);
                *(float2*)&S[(size_t)(r0 + 8) * SPAD + col] =
                    make_float2(acc[mt][nt][2] + b0, acc[mt][nt][3] + b1);
            }
        }
        __syncthreads();

        // per-thread reparam: row r, half h (64 cols)
        const int r = tid >> 1, h = tid & 1;
        const size_t grow = (size_t)m0 + r;
        const float* erow = EPS + grow * 128 + h * 64;
        float kla = 0.f;
        uint32_t zbuf[32];
#pragma unroll
        for (int j = 0; j < 32; ++j) {
            int c = h * 64 + 2 * j;
            float mu0 = S[(size_t)r * SPAD + c];
            float mu1 = S[(size_t)r * SPAD + c + 1];
            float l0  = S[(size_t)r * SPAD + c + 128];
            float l1  = S[(size_t)r * SPAD + c + 129];
            float2 ep = *(const float2*)&erow[2 * j];
            float s0 = expf(l0), s1 = expf(l1);
            float z0 = fmaf(s0, ep.x, mu0), z1 = fmaf(s1, ep.y, mu1);
            __nv_bfloat162 p = __float22bfloat162_rn(make_float2(z0, z1));
            zbuf[j] = *(uint32_t*)&p;
            kla += s0 * s0 + mu0 * mu0 - 2.f * l0 - 1.f;
            kla += s1 * s1 + mu1 * mu1 - 2.f * l1 - 1.f;
        }
        kla += __shfl_xor_sync(0xffffffffu, kla, 1);
        if (h == 0) LP[grow] = 0.5f * kla;
        __syncthreads();                         // S fully consumed

        // stage z into smem as two swizzled A-chunks (16KB each, at sbase)
#pragma unroll
        for (int cc = 0; cc < 8; ++cc) {
            uint32_t off = (uint32_t)h * 16384u +
                           (uint32_t)(r * 128 + ((cc ^ (r & 7)) << 4));
            *(int4*)(sm + off) = ((int4*)zbuf)[cc];
        }

        // triple-buffered Wd1t prefetch (buffers at +32KB, 32KB each)
        auto issue_b = [&](int nb) {
            uint32_t sB = sbase + 32768u + (uint32_t)(nb % 3) * 32768u;
            const __nv_bfloat16* Bk = W2 + (size_t)(nb * 128) * 128;
#pragma unroll
            for (int i = 0; i < 8; ++i) {
                int idx = tid + i * NTHR;        // 0..2047
                int tt = idx >> 10;              // chunk 0/1
                int rr = (idx >> 3) & 127;
                int cc = idx & 7;
                uint32_t sw = (uint32_t)(rr * 128 + ((cc ^ (rr & 7)) << 4));
                CP_ASYNC16(sB + (uint32_t)tt * 16384u + sw,
                           Bk + (size_t)rr * 128 + tt * 64 + cc * 8);
            }
            CP_COMMIT();
        };
        issue_b(0); issue_b(1);

        for (int nb = 0; nb < 8; ++nb) {
            if (nb < 7) { CP_WAIT1(); } else { CP_WAIT0(); }
            __syncthreads();                     // nb ready; nb-1 buffer free
            if (nb + 2 < 8) issue_b(nb + 2);

            uint32_t sB = sbase + 32768u + (uint32_t)(nb % 3) * 32768u;
            float acc2[4][4][4];
#pragma unroll
            for (int mt = 0; mt < 4; ++mt)
#pragma unroll
                for (int nt = 0; nt < 4; ++nt)
#pragma unroll
                    for (int q = 0; q < 4; ++q) acc2[mt][nt][q] = 0.f;

#pragma unroll
            for (int t = 0; t < 2; ++t) {
#pragma unroll
                for (int kk = 0; kk < 4; ++kk) {
                    uint32_t a[4][4];
#pragma unroll
                    for (int mt = 0; mt < 4; ++mt) {
                        int row = wm * 64 + mt * 16 + (g & 1) * 8 + lq;
                        int kc  = kk * 2 + (g >> 1);
                        uint32_t ad = sbase + (uint32_t)t * 16384u +
                                      (uint32_t)(row * 128 + ((kc ^ (row & 7)) << 4));
                        ldsm4(a[mt][0], a[mt][1], a[mt][2], a[mt][3], ad);
                    }
                    uint32_t b[4][2];
#pragma unroll
                    for (int p = 0; p < 2; ++p) {
                        int row = wn * 32 + (p * 2 + (g >> 1)) * 8 + lq;
                        int kc  = kk * 2 + (g & 1);
                        uint32_t ad = sB + (uint32_t)t * 16384u +
                                      (uint32_t)(row * 128 + ((kc ^ (row & 7)) << 4));
                        uint32_t r0, r1, r2, r3;
                        ldsm4(r0, r1, r2, r3, ad);
                        b[p * 2][0] = r0; b[p * 2][1] = r1;
                        b[p * 2 + 1][0] = r2; b[p * 2 + 1][1] = r3;
                    }
#pragma unroll
                    for (int mt = 0; mt < 4; ++mt)
#pragma unroll
                        for (int nt = 0; nt < 4; ++nt)
                            mma16816(acc2[mt][nt], a[mt], b[nt]);
                }
            }
            // store hd block
#pragma unroll
            for (int mt = 0; mt < 4; ++mt) {
                int r0 = rbase + mt * 16;
#pragma unroll
                for (int nt = 0; nt < 4; ++nt) {
                    int col = nb * 128 + wn * 32 + nt * 8 + cq;
                    float b0 = __ldg(B2 + col), b1 = __ldg(B2 + col + 1);
                    float v0 = fmaxf(acc2[mt][nt][0] + b0, 0.f);
                    float v1 = fmaxf(acc2[mt][nt][1] + b1, 0.f);
                    float v2 = fmaxf(acc2[mt][nt][2] + b0, 0.f);
                    float v3 = fmaxf(acc2[mt][nt][3] + b1, 0.f);
                    __nv_bfloat162 p0 = __float22bfloat162_rn(make_float2(v0, v1));
                    __nv_bfloat162 p1 = __float22bfloat162_rn(make_float2(v2, v3));
                    *(uint32_t*)(C2 + (size_t)r0 * D_H + col)       = *(uint32_t*)&p0;
                    *(uint32_t*)(C2 + (size_t)(r0 + 8) * D_H + col) = *(uint32_t*)&p1;
                }
            }
        }
    }
}

// ---------------- fused prep kernel ------------------------------------------
__device__ __forceinline__ void do_transpose(float (*ts)[33],
                                             const float* __restrict__ in,
                                             __nv_bfloat16* __restrict__ out,
                                             int K, int N, int rowOff, int bx, int by, int tid) {
    int tx = tid & 31, ty = tid >> 5;
    int k0 = by * 32, n0 = bx * 32;
    for (int j = ty; j < 32; j += 8)
        ts[j][tx] = in[(size_t)(k0 + j) * N + n0 + tx];
    __syncthreads();
    for (int j = ty; j < 32; j += 8)
        out[(size_t)(rowOff + n0 + j) * K + k0 + tx] = __float2bfloat16(ts[tx][j]);
}

__global__ __launch_bounds__(256)
void prep_kernel(const float* __restrict__ x,
                 const float* __restrict__ We1, const float* __restrict__ Wmu,
                 const float* __restrict__ Wls, const float* __restrict__ Wd1,
                 const float* __restrict__ Wd2, const float* __restrict__ bmu,
                 const float* __restrict__ bls,
                 __nv_bfloat16* __restrict__ xb, __nv_bfloat16* __restrict__ We1t,
                 __nv_bfloat16* __restrict__ Wmlt, __nv_bfloat16* __restrict__ Wd1t,
                 __nv_bfloat16* __restrict__ Wd2t, float* __restrict__ bml)
{
    __shared__ float ts[32][33];
    const int b = blockIdx.x, tid = threadIdx.x;
    if (b < 16384) {
        size_t i = ((size_t)b * 256 + tid) * 8;
        float4 a = *(const float4*)(x + i);
        float4 c = *(const float4*)(x + i + 4);
        __nv_bfloat162 p[4];
        p[0] = __float22bfloat162_rn(make_float2(a.x, a.y));
        p[1] = __float22bfloat162_rn(make_float2(a.z, a.w));
        p[2] = __float22bfloat162_rn(make_float2(c.x, c.y));
        p[3] = __float22bfloat162_rn(make_float2(c.z, c.w));
        *(int4*)(xb + i) = *(int4*)p;
    } else if (b < 17408) {
        int r = b - 16384;  do_transpose(ts, We1, We1t, 1024, 1024, 0,   r % 32, r / 32, tid);
    } else if (b < 17536) {
        int r = b - 17408;  do_transpose(ts, Wmu, Wmlt, 1024, 128,  0,   r % 4,  r / 4,  tid);
    } else if (b < 17664) {
        int r = b - 17536;  do_transpose(ts, Wls, Wmlt, 1024, 128,  128, r % 4,  r / 4,  tid);
    } else if (b < 17792) {
        int r = b - 17664;  do_transpose(ts, Wd1, Wd1t, 128,  1024, 0,   r % 32, r / 32, tid);
    } else if (b < 18816) {
        int r = b - 17792;  do_transpose(ts, Wd2, Wd2t, 1024, 1024, 0,   r % 32, r / 32, tid);
    } else {
        bml[tid] = (tid < 128) ? bmu[tid] : bls[tid - 128];
    }
}

__global__ void finalize_kernel(const float* __restrict__ kl_, const float* __restrict__ lp_,
                                float* __restrict__ out) {
    int r = blockIdx.x * blockDim.x + threadIdx.x;
    float s = 0.f;
#pragma unroll
    for (int j = 0; j < 32; j++) s += lp_[(size_t)r * 32 + j];
    out[r] = s - kl_[r];
}

// ---------------- launch ------------------------------------------------------
extern "C" void kernel_launch(void* const* d_in, const int* in_sizes, int n_in,
                              void* d_out, int out_size)
{
    const float* x   = (const float*)d_in[0];
    const float* eps = (const float*)d_in[1];
    const float* We1 = (const float*)d_in[2];
    const float* be1 = (const float*)d_in[3];
    const float* Wmu = (const float*)d_in[4];
    const float* bmu = (const float*)d_in[5];
    const float* Wls = (const float*)d_in[6];
    const float* bls = (const float*)d_in[7];
    const float* Wd1 = (const float*)d_in[8];
    const float* bd1 = (const float*)d_in[9];
    const float* Wd2 = (const float*)d_in[10];
    const float* bd2 = (const float*)d_in[11];
    float* out = (float*)d_out;

    __nv_bfloat16 *xb, *hb, *hdb, *We1t, *Wmlt, *Wd1t, *Wd2t;
    float *kl, *lp, *bml;
    cudaGetSymbolAddress((void**)&xb,   g_xb);
    cudaGetSymbolAddress((void**)&hb,   g_hb);
    cudaGetSymbolAddress((void**)&hdb,  g_hdb);
    cudaGetSymbolAddress((void**)&kl,   g_kl);
    cudaGetSymbolAddress((void**)&lp,   g_lp);
    cudaGetSymbolAddress((void**)&We1t, g_We1t);
    cudaGetSymbolAddress((void**)&Wmlt, g_Wmlt);
    cudaGetSymbolAddress((void**)&Wd1t, g_Wd1t);
    cudaGetSymbolAddress((void**)&Wd2t, g_Wd2t);
    cudaGetSymbolAddress((void**)&bml,  g_bml);

    constexpr int SM_SMALL = GemmCfg<128,128>::SMEM;   // 3 x 32KB + pad
    constexpr int SM_BIG   = GemmCfg<128,256>::SMEM;   // 3 x 48KB + pad

    cudaFuncSetAttribute((const void*)mma_gemm<0,128,128,2>, cudaFuncAttributeMaxDynamicSharedMemorySize, SM_SMALL);
    cudaFuncSetAttribute((const void*)mma_gemm<2,128,128,2>, cudaFuncAttributeMaxDynamicSharedMemorySize, SM_SMALL);
    cudaFuncSetAttribute((const void*)mma_gemm<3,128,256,1>, cudaFuncAttributeMaxDynamicSharedMemorySize, SM_BIG);

    // 0) fused prep
    prep_kernel<<<18817, 256>>>(x, We1, Wmu, Wls, Wd1, Wd2, bmu, bls,
                                xb, We1t, Wmlt, Wd1t, Wd2t, bml);
    // 1) h = relu(x @ We1 + be1) -> bf16
    mma_gemm<0,128,128,2><<<dim3(8, 256), NTHR, SM_SMALL>>>(
        xb, D_IN, We1t, be1, hb, D_H, nullptr, nullptr, nullptr,
        nullptr, nullptr, nullptr, D_IN);
    // 2) [mu|ls] GEMM + fused reparam/KL + hd = relu(z @ Wd1 + bd1) -> hdb
    mma_gemm<3,128,256,1><<<dim3(1, 256), NTHR, SM_BIG>>>(
        hb, D_H, Wmlt, bml, nullptr, 0, nullptr, kl, eps,
        Wd1t, bd1, hdb, D_H);
    // 3) Bernoulli log-lik partials from hd @ Wd2 + bd2
    mma_gemm<2,128,128,2><<<dim3(8, 256), NTHR, SM_SMALL>>>(
        hdb, D_H, Wd2t, bd2, nullptr, 0, xb, lp, nullptr,
        nullptr, nullptr, nullptr, D_H);
    // 4) out = log_px - kl
    finalize_kernel<<<BATCH / 256, 256>>>(kl, lp, out);
}

// round 9
// speedup vs baseline: 7.0428x; 1.0446x over previous
#include <cuda_runtime.h>
#include <cuda_bf16.h>
#include <cstdint>
#include <math.h>

#define BATCH 32768
#define D_IN  1024
#define D_H   1024
#define D_L   128

// ---------------- scratch (__device__ globals; alloc-free rule) -------------
__device__ __align__(16) __nv_bfloat16 g_xb [BATCH * D_IN];
__device__ __align__(16) __nv_bfloat16 g_hb [BATCH * D_H];
__device__ __align__(16) __nv_bfloat16 g_hdb[BATCH * D_H];
__device__ __align__(16) float         g_kl [BATCH];
__device__ __align__(16) float         g_lp [BATCH * 16];
__device__ __align__(16) __nv_bfloat16 g_We1t[D_H * D_IN];     // [N][K] K-major
__device__ __align__(16) __nv_bfloat16 g_Wmlt[256 * D_H];
__device__ __align__(16) __nv_bfloat16 g_Wd1t[D_H * D_L];
__device__ __align__(16) __nv_bfloat16 g_Wd2t[D_IN * D_H];
__device__ __align__(16) float         g_bml [256];

// ---------------- helpers ----------------------------------------------------
__device__ __forceinline__ uint32_t smem_u32(const void* p) {
    uint32_t a;
    asm("{ .reg .u64 t; cvta.to.shared.u64 t, %1; cvt.u32.u64 %0, t; }" : "=r"(a) : "l"(p));
    return a;
}

#define CP_ASYNC16(dst, src) \
    asm volatile("cp.async.cg.shared.global [%0], [%1], 16;" :: "r"(dst), "l"(src))
#define CP_COMMIT() asm volatile("cp.async.commit_group;" ::: "memory")
#define CP_WAIT0()  asm volatile("cp.async.wait_group 0;" ::: "memory")
#define CP_WAIT1()  asm volatile("cp.async.wait_group 1;" ::: "memory")

__device__ __forceinline__ void ldsm4(uint32_t& r0, uint32_t& r1, uint32_t& r2, uint32_t& r3,
                                      uint32_t addr) {
    asm volatile("ldmatrix.sync.aligned.m8n8.x4.shared.b16 {%0,%1,%2,%3}, [%4];"
                 : "=r"(r0), "=r"(r1), "=r"(r2), "=r"(r3) : "r"(addr));
}

__device__ __forceinline__ void mma16816(float* c, const uint32_t* a, const uint32_t* b) {
    asm volatile("mma.sync.aligned.m16n8k16.row.col.f32.bf16.bf16.f32 "
                 "{%0,%1,%2,%3}, {%4,%5,%6,%7}, {%8,%9}, {%0,%1,%2,%3};"
                 : "+f"(c[0]), "+f"(c[1]), "+f"(c[2]), "+f"(c[3])
                 : "r"(a[0]), "r"(a[1]), "r"(a[2]), "r"(a[3]), "r"(b[0]), "r"(b[1]));
}

// ---------------- HMMA GEMM: C[M,N] = A[M,K] @ Bt[N,K]^T (+epilogue) ---------
// Warp tile 64x64 everywhere (max register reuse, min smem traffic/MAC).
// EPI 0/2: BM=128, BN=128, NTHR=128 (4 warps, 2x2 grid), MINB=2 (2 CTA/SM).
// EPI 3:   BM=128, BN=256, NTHR=256 (8 warps, 2x4 grid), MINB=1,
//          fused reparam + KL + hd = relu(z @ W2^T + B2) -> C2.
// 3-stage cp.async pipeline, ONE __syncthreads per K-chunk of 64.
static constexpr int NSTAGE = 3;

template<int BM, int BN> struct GemmCfg {
    static constexpr int STAGE = (BM + BN) * 64 * 2;
    static constexpr int SMEM  = NSTAGE * STAGE + 128;
};

template<int EPI, int BM, int BN, int NTHR, int MINB>
__global__ __launch_bounds__(NTHR, MINB)
void mma_gemm(const __nv_bfloat16* __restrict__ A, int lda,
              const __nv_bfloat16* __restrict__ Bt,
              const float* __restrict__ bias,
              void* __restrict__ Cv, int ldc,
              const __nv_bfloat16* __restrict__ XB,
              float* __restrict__ LP,
              const float* __restrict__ EPS,
              const __nv_bfloat16* __restrict__ W2,
              const float* __restrict__ B2,
              __nv_bfloat16* __restrict__ C2, int K)
{
    extern __shared__ char smraw[];
    uint32_t raw = smem_u32(smraw);
    uint32_t sbase = (raw + 127u) & ~127u;
    char* sm = smraw + (sbase - raw);

    constexpr int NWARP = NTHR / 32;
    constexpr int WM  = 2;                     // warp rows
    constexpr int WNG = NWARP / WM;            // warp cols
    constexpr int WTN = BN / WNG;              // warp N tile (64)
    constexpr int NT  = WTN / 8;               // mma n-tiles per warp (8)
    constexpr int BLD = WTN / 16;              // B ldsm4 per kk (4)
    constexpr int A_BYTES = BM * 64 * 2;
    constexpr int STAGE_BYTES = GemmCfg<BM, BN>::STAGE;
    constexpr int AI = BM * 8 / NTHR, BI = BN * 8 / NTHR;

    const int tid  = threadIdx.x, lane = tid & 31, wid = tid >> 5;
    const int wm   = wid % WM, wn = wid / WM;
    const int bn   = blockIdx.x;
    const int m0   = blockIdx.y * BM, col0 = bn * BN;

    const __nv_bfloat16* Ag = A  + (size_t)m0   * lda;
    const __nv_bfloat16* Bg = Bt + (size_t)col0 * K;

    const int T = K >> 6;
    const int P = (T < NSTAGE - 1) ? T : (NSTAGE - 1);

    float acc[4][NT][4];
#pragma unroll
    for (int mt = 0; mt < 4; ++mt)
#pragma unroll
        for (int nt = 0; nt < NT; ++nt)
#pragma unroll
            for (int q = 0; q < 4; ++q) acc[mt][nt][q] = 0.f;

    auto issue_stage = [&](int kt) {
        uint32_t sA = sbase + (uint32_t)(kt % NSTAGE) * STAGE_BYTES;
        uint32_t sB = sA + A_BYTES;
        const __nv_bfloat16* Ak = Ag + kt * 64;
        const __nv_bfloat16* Bk = Bg + kt * 64;
#pragma unroll
        for (int i = 0; i < AI; ++i) {
            int idx = tid + i * NTHR;
            int rr = idx >> 3, cc = idx & 7;
            uint32_t sw = (uint32_t)(rr * 128 + ((cc ^ (rr & 7)) << 4));
            CP_ASYNC16(sA + sw, Ak + (size_t)rr * lda + cc * 8);
        }
#pragma unroll
        for (int i = 0; i < BI; ++i) {
            int idx = tid + i * NTHR;
            int rr = idx >> 3, cc = idx & 7;
            uint32_t sw = (uint32_t)(rr * 128 + ((cc ^ (rr & 7)) << 4));
            CP_ASYNC16(sB + sw, Bk + (size_t)rr * K + cc * 8);
        }
        CP_COMMIT();
    };

    for (int kt = 0; kt < P; ++kt) issue_stage(kt);
    int committed = P;

    const int g = lane >> 3, lq = lane & 7;

    for (int t = 0; t < T; ++t) {
        int allow = committed - t - 1;
        if (allow >= 1) { CP_WAIT1(); } else { CP_WAIT0(); }
        __syncthreads();

        if (t + NSTAGE - 1 < T) { issue_stage(t + NSTAGE - 1); committed++; }

        uint32_t sA = sbase + (uint32_t)(t % NSTAGE) * STAGE_BYTES;
        uint32_t sB = sA + A_BYTES;

#pragma unroll
        for (int kk = 0; kk < 4; ++kk) {
            uint32_t a[4][4];
#pragma unroll
            for (int mt = 0; mt < 4; ++mt) {
                int row = wm * 64 + mt * 16 + (g & 1) * 8 + lq;
                int kc  = kk * 2 + (g >> 1);
                uint32_t ad = sA + (uint32_t)(row * 128 + ((kc ^ (row & 7)) << 4));
                ldsm4(a[mt][0], a[mt][1], a[mt][2], a[mt][3], ad);
            }
            uint32_t b[NT][2];
#pragma unroll
            for (int p = 0; p < BLD; ++p) {
                int row = wn * WTN + (p * 2 + (g >> 1)) * 8 + lq;
                int kc  = kk * 2 + (g & 1);
                uint32_t ad = sB + (uint32_t)(row * 128 + ((kc ^ (row & 7)) << 4));
                uint32_t r0, r1, r2, r3;
                ldsm4(r0, r1, r2, r3, ad);
                b[p * 2][0] = r0; b[p * 2][1] = r1;
                b[p * 2 + 1][0] = r2; b[p * 2 + 1][1] = r3;
            }
#pragma unroll
            for (int mt = 0; mt < 4; ++mt)
#pragma unroll
                for (int nt = 0; nt < NT; ++nt)
                    mma16816(acc[mt][nt], a[mt], b[nt]);
        }
    }

    // ---------------- epilogue ----------------
    const int rbase = m0 + wm * 64 + (lane >> 2);
    const int cq    = (lane & 3) * 2;

    if (EPI == 0) {
        __nv_bfloat16* C = (__nv_bfloat16*)Cv;
#pragma unroll
        for (int mt = 0; mt < 4; ++mt) {
            int r0 = rbase + mt * 16;
#pragma unroll
            for (int nt = 0; nt < NT; ++nt) {
                int col = col0 + wn * WTN + nt * 8 + cq;
                float b0 = __ldg(bias + col), b1 = __ldg(bias + col + 1);
                float v0 = fmaxf(acc[mt][nt][0] + b0, 0.f);
                float v1 = fmaxf(acc[mt][nt][1] + b1, 0.f);
                float v2 = fmaxf(acc[mt][nt][2] + b0, 0.f);
                float v3 = fmaxf(acc[mt][nt][3] + b1, 0.f);
                __nv_bfloat162 p0 = __float22bfloat162_rn(make_float2(v0, v1));
                __nv_bfloat162 p1 = __float22bfloat162_rn(make_float2(v2, v3));
                *(uint32_t*)(C + (size_t)r0 * ldc + col)       = *(uint32_t*)&p0;
                *(uint32_t*)(C + (size_t)(r0 + 8) * ldc + col) = *(uint32_t*)&p1;
            }
        }
    } else if (EPI == 2) {
#pragma unroll
        for (int mt = 0; mt < 4; ++mt) {
            int r0 = rbase + mt * 16;
            float s0 = 0.f, s1 = 0.f;
#pragma unroll
            for (int nt = 0; nt < NT; ++nt) {
                int col = col0 + wn * WTN + nt * 8 + cq;
                float b0 = __ldg(bias + col), b1 = __ldg(bias + col + 1);
                uint32_t xw0 = *(const uint32_t*)(XB + (size_t)r0 * D_IN + col);
                uint32_t xw1 = *(const uint32_t*)(XB + (size_t)(r0 + 8) * D_IN + col);
                __nv_bfloat162 xp0 = *(__nv_bfloat162*)&xw0;
                __nv_bfloat162 xp1 = *(__nv_bfloat162*)&xw1;
                float a0 = acc[mt][nt][0] + b0, a1 = acc[mt][nt][1] + b1;
                float a2 = acc[mt][nt][2] + b0, a3 = acc[mt][nt][3] + b1;
                float t0 = (__bfloat162float(xp0.x) > 0.5f) ? -a0 : a0;
                float t1 = (__bfloat162float(xp0.y) > 0.5f) ? -a1 : a1;
                float t2 = (__bfloat162float(xp1.x) > 0.5f) ? -a2 : a2;
                float t3 = (__bfloat162float(xp1.y) > 0.5f) ? -a3 : a3;
                s0 += fmaxf(t0, 0.f) + log1pf(__expf(-fabsf(t0)));
                s0 += fmaxf(t1, 0.f) + log1pf(__expf(-fabsf(t1)));
                s1 += fmaxf(t2, 0.f) + log1pf(__expf(-fabsf(t2)));
                s1 += fmaxf(t3, 0.f) + log1pf(__expf(-fabsf(t3)));
            }
            s0 += __shfl_xor_sync(0xffffffffu, s0, 1);
            s0 += __shfl_xor_sync(0xffffffffu, s0, 2);
            s1 += __shfl_xor_sync(0xffffffffu, s1, 1);
            s1 += __shfl_xor_sync(0xffffffffu, s1, 2);
            if ((lane & 3) == 0) {
                LP[(size_t)r0 * 16 + bn * 2 + wn]       = -s0;
                LP[(size_t)(r0 + 8) * 16 + bn * 2 + wn] = -s1;
            }
        }
    } else {
        // EPI 3: fused reparam + KL + hd GEMM. BM=128, BN=256 (mu|ls), NTHR=256.
        constexpr int SPAD = 258;
        float* S = (float*)sm;
        __syncthreads();
        const int rl = wm * 64 + (lane >> 2);
#pragma unroll
        for (int mt = 0; mt < 4; ++mt) {
            int r0 = rl + mt * 16;
#pragma unroll
            for (int nt = 0; nt < NT; ++nt) {
                int col = wn * WTN + nt * 8 + cq;
                float b0 = __ldg(bias + col), b1 = __ldg(bias + col + 1);
                *(float2*)&S[(size_t)r0 * SPAD + col] =
                    make_float2(acc[mt][nt][0] + b0, acc[mt][nt][1] + b1);
                *(float2*)&S[(size_t)(r0 + 8) * SPAD + col] =
                    make_float2(acc[mt][nt][2] + b0, acc[mt][nt][3] + b1);
            }
        }
        __syncthreads();

        // per-thread reparam: row r, half h (64 cols)
        const int r = tid >> 1, h = tid & 1;
        const size_t grow = (size_t)m0 + r;
        const float* erow = EPS + grow * 128 + h * 64;
        float kla = 0.f;
        uint32_t zbuf[32];
#pragma unroll
        for (int j = 0; j < 32; ++j) {
            int c = h * 64 + 2 * j;
            float mu0 = S[(size_t)r * SPAD + c];
            float mu1 = S[(size_t)r * SPAD + c + 1];
            float l0  = S[(size_t)r * SPAD + c + 128];
            float l1  = S[(size_t)r * SPAD + c + 129];
            float2 ep = *(const float2*)&erow[2 * j];
            float s0 = expf(l0), s1 = expf(l1);
            float z0 = fmaf(s0, ep.x, mu0), z1 = fmaf(s1, ep.y, mu1);
            __nv_bfloat162 p = __float22bfloat162_rn(make_float2(z0, z1));
            zbuf[j] = *(uint32_t*)&p;
            kla += s0 * s0 + mu0 * mu0 - 2.f * l0 - 1.f;
            kla += s1 * s1 + mu1 * mu1 - 2.f * l1 - 1.f;
        }
        kla += __shfl_xor_sync(0xffffffffu, kla, 1);
        if (h == 0) LP[grow] = 0.5f * kla;
        __syncthreads();                         // S fully consumed

        // stage z into smem as two swizzled A-chunks (16KB each, at sbase)
#pragma unroll
        for (int cc = 0; cc < 8; ++cc) {
            uint32_t off = (uint32_t)h * 16384u +
                           (uint32_t)(r * 128 + ((cc ^ (r & 7)) << 4));
            *(int4*)(sm + off) = ((int4*)zbuf)[cc];
        }

        // triple-buffered Wd1t prefetch (buffers at +32KB, 32KB each)
        auto issue_b = [&](int nb) {
            uint32_t sB = sbase + 32768u + (uint32_t)(nb % 3) * 32768u;
            const __nv_bfloat16* Bk = W2 + (size_t)(nb * 128) * 128;
#pragma unroll
            for (int i = 0; i < 2048 / NTHR; ++i) {
                int idx = tid + i * NTHR;        // 0..2047
                int tt = idx >> 10;              // chunk 0/1
                int rr = (idx >> 3) & 127;
                int cc = idx & 7;
                uint32_t sw = (uint32_t)(rr * 128 + ((cc ^ (rr & 7)) << 4));
                CP_ASYNC16(sB + (uint32_t)tt * 16384u + sw,
                           Bk + (size_t)rr * 128 + tt * 64 + cc * 8);
            }
            CP_COMMIT();
        };
        issue_b(0); issue_b(1);

        for (int nb = 0; nb < 8; ++nb) {
            if (nb < 7) { CP_WAIT1(); } else { CP_WAIT0(); }
            __syncthreads();
            if (nb + 2 < 8) issue_b(nb + 2);

            uint32_t sB = sbase + 32768u + (uint32_t)(nb % 3) * 32768u;
            float acc2[4][4][4];
#pragma unroll
            for (int mt = 0; mt < 4; ++mt)
#pragma unroll
                for (int nt = 0; nt < 4; ++nt)
#pragma unroll
                    for (int q = 0; q < 4; ++q) acc2[mt][nt][q] = 0.f;

#pragma unroll
            for (int t = 0; t < 2; ++t) {
#pragma unroll
                for (int kk = 0; kk < 4; ++kk) {
                    uint32_t a[4][4];
#pragma unroll
                    for (int mt = 0; mt < 4; ++mt) {
                        int row = wm * 64 + mt * 16 + (g & 1) * 8 + lq;
                        int kc  = kk * 2 + (g >> 1);
                        uint32_t ad = sbase + (uint32_t)t * 16384u +
                                      (uint32_t)(row * 128 + ((kc ^ (row & 7)) << 4));
                        ldsm4(a[mt][0], a[mt][1], a[mt][2], a[mt][3], ad);
                    }
                    uint32_t b[4][2];
#pragma unroll
                    for (int p = 0; p < 2; ++p) {
                        int row = wn * 32 + (p * 2 + (g >> 1)) * 8 + lq;
                        int kc  = kk * 2 + (g & 1);
                        uint32_t ad = sB + (uint32_t)t * 16384u +
                                      (uint32_t)(row * 128 + ((kc ^ (row & 7)) << 4));
                        uint32_t r0, r1, r2, r3;
                        ldsm4(r0, r1, r2, r3, ad);
                        b[p * 2][0] = r0; b[p * 2][1] = r1;
                        b[p * 2 + 1][0] = r2; b[p * 2 + 1][1] = r3;
                    }
#pragma unroll
                    for (int mt = 0; mt < 4; ++mt)
#pragma unroll
                        for (int nt = 0; nt < 4; ++nt)
                            mma16816(acc2[mt][nt], a[mt], b[nt]);
                }
            }
#pragma unroll
            for (int mt = 0; mt < 4; ++mt) {
                int r0 = rbase + mt * 16;
#pragma unroll
                for (int nt = 0; nt < 4; ++nt) {
                    int col = nb * 128 + wn * 32 + nt * 8 + cq;
                    float b0 = __ldg(B2 + col), b1 = __ldg(B2 + col + 1);
                    float v0 = fmaxf(acc2[mt][nt][0] + b0, 0.f);
                    float v1 = fmaxf(acc2[mt][nt][1] + b1, 0.f);
                    float v2 = fmaxf(acc2[mt][nt][2] + b0, 0.f);
                    float v3 = fmaxf(acc2[mt][nt][3] + b1, 0.f);
                    __nv_bfloat162 p0 = __float22bfloat162_rn(make_float2(v0, v1));
                    __nv_bfloat162 p1 = __float22bfloat162_rn(make_float2(v2, v3));
                    *(uint32_t*)(C2 + (size_t)r0 * D_H + col)       = *(uint32_t*)&p0;
                    *(uint32_t*)(C2 + (size_t)(r0 + 8) * D_H + col) = *(uint32_t*)&p1;
                }
            }
        }
    }
}

// ---------------- fused prep kernel ------------------------------------------
__device__ __forceinline__ void do_transpose(float (*ts)[33],
                                             const float* __restrict__ in,
                                             __nv_bfloat16* __restrict__ out,
                                             int K, int N, int rowOff, int bx, int by, int tid) {
    int tx = tid & 31, ty = tid >> 5;
    int k0 = by * 32, n0 = bx * 32;
    for (int j = ty; j < 32; j += 8)
        ts[j][tx] = in[(size_t)(k0 + j) * N + n0 + tx];
    __syncthreads();
    for (int j = ty; j < 32; j += 8)
        out[(size_t)(rowOff + n0 + j) * K + k0 + tx] = __float2bfloat16(ts[tx][j]);
}

__global__ __launch_bounds__(256)
void prep_kernel(const float* __restrict__ x,
                 const float* __restrict__ We1, const float* __restrict__ Wmu,
                 const float* __restrict__ Wls, const float* __restrict__ Wd1,
                 const float* __restrict__ Wd2, const float* __restrict__ bmu,
                 const float* __restrict__ bls,
                 __nv_bfloat16* __restrict__ xb, __nv_bfloat16* __restrict__ We1t,
                 __nv_bfloat16* __restrict__ Wmlt, __nv_bfloat16* __restrict__ Wd1t,
                 __nv_bfloat16* __restrict__ Wd2t, float* __restrict__ bml)
{
    __shared__ float ts[32][33];
    const int b = blockIdx.x, tid = threadIdx.x;
    if (b < 16384) {
        size_t i = ((size_t)b * 256 + tid) * 8;
        float4 a = *(const float4*)(x + i);
        float4 c = *(const float4*)(x + i + 4);
        __nv_bfloat162 p[4];
        p[0] = __float22bfloat162_rn(make_float2(a.x, a.y));
        p[1] = __float22bfloat162_rn(make_float2(a.z, a.w));
        p[2] = __float22bfloat162_rn(make_float2(c.x, c.y));
        p[3] = __float22bfloat162_rn(make_float2(c.z, c.w));
        *(int4*)(xb + i) = *(int4*)p;
    } else if (b < 17408) {
        int r = b - 16384;  do_transpose(ts, We1, We1t, 1024, 1024, 0,   r % 32, r / 32, tid);
    } else if (b < 17536) {
        int r = b - 17408;  do_transpose(ts, Wmu, Wmlt, 1024, 128,  0,   r % 4,  r / 4,  tid);
    } else if (b < 17664) {
        int r = b - 17536;  do_transpose(ts, Wls, Wmlt, 1024, 128,  128, r % 4,  r / 4,  tid);
    } else if (b < 17792) {
        int r = b - 17664;  do_transpose(ts, Wd1, Wd1t, 128,  1024, 0,   r % 32, r / 32, tid);
    } else if (b < 18816) {
        int r = b - 17792;  do_transpose(ts, Wd2, Wd2t, 1024, 1024, 0,   r % 32, r / 32, tid);
    } else {
        bml[tid] = (tid < 128) ? bmu[tid] : bls[tid - 128];
    }
}

__global__ void finalize_kernel(const float* __restrict__ kl_, const float* __restrict__ lp_,
                                float* __restrict__ out) {
    int r = blockIdx.x * blockDim.x + threadIdx.x;
    float s = 0.f;
#pragma unroll
    for (int j = 0; j < 16; j++) s += lp_[(size_t)r * 16 + j];
    out[r] = s - kl_[r];
}

// ---------------- launch ------------------------------------------------------
extern "C" void kernel_launch(void* const* d_in, const int* in_sizes, int n_in,
                              void* d_out, int out_size)
{
    const float* x   = (const float*)d_in[0];
    const float* eps = (const float*)d_in[1];
    const float* We1 = (const float*)d_in[2];
    const float* be1 = (const float*)d_in[3];
    const float* Wmu = (const float*)d_in[4];
    const float* bmu = (const float*)d_in[5];
    const float* Wls = (const float*)d_in[6];
    const float* bls = (const float*)d_in[7];
    const float* Wd1 = (const float*)d_in[8];
    const float* bd1 = (const float*)d_in[9];
    const float* Wd2 = (const float*)d_in[10];
    const float* bd2 = (const float*)d_in[11];
    float* out = (float*)d_out;

    __nv_bfloat16 *xb, *hb, *hdb, *We1t, *Wmlt, *Wd1t, *Wd2t;
    float *kl, *lp, *bml;
    cudaGetSymbolAddress((void**)&xb,   g_xb);
    cudaGetSymbolAddress((void**)&hb,   g_hb);
    cudaGetSymbolAddress((void**)&hdb,  g_hdb);
    cudaGetSymbolAddress((void**)&kl,   g_kl);
    cudaGetSymbolAddress((void**)&lp,   g_lp);
    cudaGetSymbolAddress((void**)&We1t, g_We1t);
    cudaGetSymbolAddress((void**)&Wmlt, g_Wmlt);
    cudaGetSymbolAddress((void**)&Wd1t, g_Wd1t);
    cudaGetSymbolAddress((void**)&Wd2t, g_Wd2t);
    cudaGetSymbolAddress((void**)&bml,  g_bml);

    constexpr int SM_SMALL = GemmCfg<128,128>::SMEM;   // 3 x 32KB + pad
    constexpr int SM_BIG   = GemmCfg<128,256>::SMEM;   // 3 x 48KB + pad

    cudaFuncSetAttribute((const void*)mma_gemm<0,128,128,128,2>, cudaFuncAttributeMaxDynamicSharedMemorySize, SM_SMALL);
    cudaFuncSetAttribute((const void*)mma_gemm<2,128,128,128,2>, cudaFuncAttributeMaxDynamicSharedMemorySize, SM_SMALL);
    cudaFuncSetAttribute((const void*)mma_gemm<3,128,256,256,1>, cudaFuncAttributeMaxDynamicSharedMemorySize, SM_BIG);

    // 0) fused prep
    prep_kernel<<<18817, 256>>>(x, We1, Wmu, Wls, Wd1, Wd2, bmu, bls,
                                xb, We1t, Wmlt, Wd1t, Wd2t, bml);
    // 1) h = relu(x @ We1 + be1) -> bf16
    mma_gemm<0,128,128,128,2><<<dim3(8, 256), 128, SM_SMALL>>>(
        xb, D_IN, We1t, be1, hb, D_H, nullptr, nullptr, nullptr,
        nullptr, nullptr, nullptr, D_IN);
    // 2) [mu|ls] GEMM + fused reparam/KL + hd = relu(z @ Wd1 + bd1) -> hdb
    mma_gemm<3,128,256,256,1><<<dim3(1, 256), 256, SM_BIG>>>(
        hb, D_H, Wmlt, bml, nullptr, 0, nullptr, kl, eps,
        Wd1t, bd1, hdb, D_H);
    // 3) Bernoulli log-lik partials from hd @ Wd2 + bd2
    mma_gemm<2,128,128,128,2><<<dim3(8, 256), 128, SM_SMALL>>>(
        hdb, D_H, Wd2t, bd2, nullptr, 0, xb, lp, nullptr,
        nullptr, nullptr, nullptr, D_H);
    // 4) out = log_px - kl
    finalize_kernel<<<BATCH / 256, 256>>>(kl, lp, out);
}